// round 12
// baseline (speedup 1.0000x reference)
#include <cuda_runtime.h>
#include <cuda_bf16.h>
#include <math.h>
#include <stdint.h>

#define Tn 1024
#define Bn 256

// ---------------- static device scratch ----------------
__device__ __align__(128) float g_pv[46 * 3 * 256];
__device__ __align__(128) float g_pa[16 * 3 * 256];
__device__ __align__(128) float g_pb[256 * 3 * 256];
__device__ __align__(128) __nv_bfloat16 g_Wb_hi[768 * 256];
__device__ __align__(128) __nv_bfloat16 g_Wb_lo[768 * 256];
__device__ __align__(128) float g_u[768];
__device__ __align__(128) __nv_bfloat16 g_h_hi[(size_t)262144 * 256];
__device__ __align__(128) __nv_bfloat16 g_h_lo[(size_t)262144 * 256];
__device__ __align__(128) float g_gi[(size_t)262144 * 768];

// fast, overflow-safe activations (MUFU-based; rel err ~1e-6)
__device__ __forceinline__ float sigm_f(float x) {
    return __fdividef(1.f, 1.f + __expf(-x));
}
__device__ __forceinline__ float tanh_f(float x) {
    float t = __expf(-2.f * fabsf(x));
    float r = __fdividef(1.f - t, 1.f + t);
    return copysignf(r, x);
}

// ---------------- K_setup ----------------
__global__ void k_setup(const float* __restrict__ ph, const float* __restrict__ spt,
                        const int* __restrict__ sid, const float* __restrict__ w,
                        const float* __restrict__ Wih) {
    int bid = blockIdx.x, c = threadIdx.x;
    if (bid < 138) {
        int p = bid / 3, k = bid % 3;
        float a = 0.f;
#pragma unroll 8
        for (int e = 0; e < 64; e++) a = fmaf(ph[p * 64 + e], w[c * 396 + e * 3 + k], a);
        g_pv[(p * 3 + k) * 256 + c] = a;
    } else if (bid < 186) {
        int m = (bid - 138) / 3, k = (bid - 138) % 3;
        float a = 0.f;
#pragma unroll
        for (int bit = 0; bit < 4; bit++)
            if ((m >> bit) & 1) a += w[c * 396 + (64 + bit) * 3 + k];
        g_pa[(m * 3 + k) * 256 + c] = a;
    } else if (bid < 954) {
        int b = (bid - 186) / 3, k = (bid - 186) % 3;
        int s0 = sid[b];
        float a = 0.f;
#pragma unroll 8
        for (int s = 0; s < 64; s++) a = fmaf(spt[s0 * 64 + s], w[c * 396 + (68 + s) * 3 + k], a);
        g_pb[(b * 3 + k) * 256 + c] = a;
    } else {
        int g = bid - 954;
        float v = Wih[g * 257 + c];
        __nv_bfloat16 hi = __float2bfloat16(v);
        __nv_bfloat16 lo = __float2bfloat16(v - __bfloat162float(hi));
        g_Wb_hi[g * 256 + c] = hi;
        g_Wb_lo[g * 256 + c] = lo;
        if (c == 0) g_u[g] = Wih[g * 257 + 256];
    }
}

// ---------------- K1: encoder (4 timesteps per block) ----------------
__global__ void k_enc(const int* __restrict__ vw, const int* __restrict__ cs,
                      const int* __restrict__ sa, const int* __restrict__ ea,
                      const int* __restrict__ sap, const int* __restrict__ eap,
                      const float* __restrict__ encb) {
    int t0 = blockIdx.x * 4, b = blockIdx.y, c = threadIdx.x;
    float bias = encb[c];
#pragma unroll
    for (int tt = 0; tt < 4; tt++) {
        int t = t0 + tt;
        float a = bias;
#pragma unroll
        for (int k = 0; k < 3; k++) {
            int tp = t + k - 1;
            if (tp < 0 || tp >= Tn) continue;
            int o = b * Tn + tp;
            int iv = vw[o] + 1;
            int ic = cs[o] + 1;
            int ia = sa[o] + 2 * ea[o] + 4 * sap[o] + 8 * eap[o];
            a += g_pv[(iv * 3 + k) * 256 + c] + g_pv[(ic * 3 + k) * 256 + c] +
                 g_pa[(ia * 3 + k) * 256 + c] + g_pb[(b * 3 + k) * 256 + c];
        }
        a = fmaxf(a, 0.f);
        __nv_bfloat16 hi = __float2bfloat16(a);
        __nv_bfloat16 lo = __float2bfloat16(a - __bfloat162float(hi));
        size_t idx = ((size_t)(t * 256 + b)) * 256 + c;
        g_h_hi[idx] = hi;
        g_h_lo[idx] = lo;
    }
}

// ---------------- mma helpers ----------------
__device__ __forceinline__ void ldsm4(uint32_t addr, uint32_t& r0, uint32_t& r1,
                                      uint32_t& r2, uint32_t& r3) {
    asm volatile("ldmatrix.sync.aligned.m8n8.x4.shared.b16 {%0,%1,%2,%3}, [%4];"
                 : "=r"(r0), "=r"(r1), "=r"(r2), "=r"(r3) : "r"(addr));
}
__device__ __forceinline__ void mma_bf16(float* c, uint32_t a0, uint32_t a1, uint32_t a2,
                                         uint32_t a3, uint32_t b0, uint32_t b1) {
    asm volatile("mma.sync.aligned.m16n8k16.row.col.f32.bf16.bf16.f32 "
                 "{%0,%1,%2,%3}, {%4,%5,%6,%7}, {%8,%9}, {%0,%1,%2,%3};"
                 : "+f"(c[0]), "+f"(c[1]), "+f"(c[2]), "+f"(c[3])
                 : "r"(a0), "r"(a1), "r"(a2), "r"(a3), "r"(b0), "r"(b1));
}

// ---------------- K2: tensor-core bf16-split GEMM (2 n-blocks per CTA) ----------------
#define ASTR 40

__global__ __launch_bounds__(256, 2) void k_gemm(const float* __restrict__ bih,
                                                 const float* __restrict__ bhh) {
    __shared__ __nv_bfloat16 Ah[128 * ASTR], Al[128 * ASTR];
    __shared__ __nv_bfloat16 Bh[128 * ASTR], Bl[128 * ASTR];
    int tid = threadIdx.x, lane = tid & 31, wid = tid >> 5;
    size_t m0 = (size_t)blockIdx.y * 128;
    int wm = (wid & 1) * 64, wn = (wid >> 1) * 32;

    uint32_t aHiB = (uint32_t)__cvta_generic_to_shared(Ah);
    uint32_t aLoB = (uint32_t)__cvta_generic_to_shared(Al);
    uint32_t bHiB = (uint32_t)__cvta_generic_to_shared(Bh);
    uint32_t bLoB = (uint32_t)__cvta_generic_to_shared(Bl);

    for (int nb = 0; nb < 2; nb++) {
        int n0 = (blockIdx.x * 2 + nb) * 128;

        float acc[4][4][4];
#pragma unroll
        for (int i = 0; i < 4; i++)
#pragma unroll
            for (int j = 0; j < 4; j++)
#pragma unroll
                for (int r = 0; r < 4; r++) acc[i][j][r] = 0.f;

        for (int kt = 0; kt < 8; kt++) {
            __syncthreads();
#pragma unroll
            for (int h = 0; h < 2; h++) {
                int q = tid + h * 256;
                int row = q >> 2, c = q & 3;
                size_t gsrc = (m0 + row) * 256 + kt * 32 + c * 8;
                *(uint4*)&Ah[row * ASTR + c * 8] = *(const uint4*)&g_h_hi[gsrc];
                *(uint4*)&Al[row * ASTR + c * 8] = *(const uint4*)&g_h_lo[gsrc];
                size_t bsrc = (size_t)(n0 + row) * 256 + kt * 32 + c * 8;
                *(uint4*)&Bh[row * ASTR + c * 8] = *(const uint4*)&g_Wb_hi[bsrc];
                *(uint4*)&Bl[row * ASTR + c * 8] = *(const uint4*)&g_Wb_lo[bsrc];
            }
            __syncthreads();

#pragma unroll
            for (int s = 0; s < 2; s++) {
                uint32_t bh[8], bl[8];
#pragma unroll
                for (int nh = 0; nh < 2; nh++) {
                    int row = wn + nh * 16 + (lane >> 4) * 8 + (lane & 7);
                    int kc8 = (lane >> 3) & 1;
                    uint32_t off = (uint32_t)(row * ASTR + s * 16 + kc8 * 8) * 2;
                    ldsm4(bHiB + off, bh[nh * 4 + 0], bh[nh * 4 + 1], bh[nh * 4 + 2], bh[nh * 4 + 3]);
                    ldsm4(bLoB + off, bl[nh * 4 + 0], bl[nh * 4 + 1], bl[nh * 4 + 2], bl[nh * 4 + 3]);
                }
#pragma unroll
                for (int mi = 0; mi < 4; mi++) {
                    int row = wm + mi * 16 + ((lane >> 3) & 1) * 8 + (lane & 7);
                    int kc8 = lane >> 4;
                    uint32_t off = (uint32_t)(row * ASTR + s * 16 + kc8 * 8) * 2;
                    uint32_t ah0, ah1, ah2, ah3, al0, al1, al2, al3;
                    ldsm4(aHiB + off, ah0, ah1, ah2, ah3);
                    ldsm4(aLoB + off, al0, al1, al2, al3);
#pragma unroll
                    for (int ni = 0; ni < 4; ni++) {
                        uint32_t b0h = bh[ni * 2], b1h = bh[ni * 2 + 1];
                        uint32_t b0l = bl[ni * 2], b1l = bl[ni * 2 + 1];
                        mma_bf16(acc[mi][ni], ah0, ah1, ah2, ah3, b0h, b1h);
                        mma_bf16(acc[mi][ni], ah0, ah1, ah2, ah3, b0l, b1l);
                        mma_bf16(acc[mi][ni], al0, al1, al2, al3, b0h, b1h);
                    }
                }
            }
        }

        float bs0[4], bs1[4];
#pragma unroll
        for (int ni = 0; ni < 4; ni++) {
            int nc = n0 + wn + ni * 8 + (lane & 3) * 2;
            bs0[ni] = bih[nc] + (nc < 512 ? bhh[nc] : 0.f);
            bs1[ni] = bih[nc + 1] + (nc + 1 < 512 ? bhh[nc + 1] : 0.f);
        }
#pragma unroll
        for (int mi = 0; mi < 4; mi++) {
#pragma unroll
            for (int ni = 0; ni < 4; ni++) {
                int r = lane >> 2;
                int nc = n0 + wn + ni * 8 + (lane & 3) * 2;
                size_t row0 = m0 + wm + mi * 16 + r;
                float2 v0 = {acc[mi][ni][0] + bs0[ni], acc[mi][ni][1] + bs1[ni]};
                float2 v1 = {acc[mi][ni][2] + bs0[ni], acc[mi][ni][3] + bs1[ni]};
                *(float2*)&g_gi[row0 * 768 + nc] = v0;
                *(float2*)&g_gi[(row0 + 8) * 768 + nc] = v1;
            }
        }
        __syncthreads();
    }
}

// ---------------- K3: tensor-core GRU v8 (mbarrier cluster sync) ----------------
// 32 clusters x 4 CTAs, 384 threads (12 warps, one m16 tile each).
// Register-resident W; fast activations; double-buffered H;
// per-step sync = syncthreads + tid0 release-arrive x4 + try_wait (no L1 flush).
#define BSTR 264
#define OFF_WHI 0
#define OFF_WLO 101376
#define OFF_H   202752          // H[buf]: buf*HBUF; hi at +0, lo at +4224
#define HBUF    8448
#define OFF_PRE 219648          // s_pre[192][9] f32 = 6912
#define OFF_F0S 226560          // f0stage[2][8][36] f32 = 2304
#define OFF_MBAR 228864         // 8B mbarrier
#define SMEM3_BYTES 228880

__device__ __forceinline__ void stc32(uint32_t addr, uint32_t v) {
    asm volatile("st.shared::cluster.b32 [%0], %1;" :: "r"(addr), "r"(v));
}
__device__ __forceinline__ void sts32(uint32_t addr, uint32_t v) {
    asm volatile("st.shared.b32 [%0], %1;" :: "r"(addr), "r"(v));
}
__device__ __forceinline__ void mbar_init(uint32_t addr, uint32_t cnt) {
    asm volatile("mbarrier.init.shared.b64 [%0], %1;" :: "r"(addr), "r"(cnt) : "memory");
}
__device__ __forceinline__ void mbar_arrive_cluster(uint32_t addr) {
    asm volatile("mbarrier.arrive.release.cluster.shared::cluster.b64 _, [%0];"
                 :: "r"(addr) : "memory");
}
__device__ __forceinline__ void mbar_wait(uint32_t addr, uint32_t parity) {
    asm volatile(
        "{\n\t.reg .pred P;\n\t"
        "WL_%=:\n\t"
        "mbarrier.try_wait.parity.acquire.cluster.shared::cta.b64 P, [%0], %1;\n\t"
        "@!P bra WL_%=;\n\t"
        "}" :: "r"(addr), "r"(parity) : "memory");
}

__global__ void __cluster_dims__(4, 1, 1) __launch_bounds__(384, 1)
k_gru(const float* __restrict__ hid0, const float* __restrict__ Whh,
      const float* __restrict__ bhh, const float* __restrict__ pw,
      const float* __restrict__ pb, float* __restrict__ out) {
    extern __shared__ char smem[];
    __nv_bfloat16* Whi = (__nv_bfloat16*)(smem + OFF_WHI);
    __nv_bfloat16* Wlo = (__nv_bfloat16*)(smem + OFF_WLO);
    float* s_pre = (float*)(smem + OFF_PRE);
    float* f0stage = (float*)(smem + OFF_F0S);

    int tid = threadIdx.x, lane = tid & 31, wid = tid >> 5;
    int cid = blockIdx.x >> 2, rank = blockIdx.x & 3;
    int b0 = cid * 8, gj0 = rank * 64;

    uint32_t smemB = (uint32_t)__cvta_generic_to_shared(smem);
    if (tid == 0) mbar_init(smemB + OFF_MBAR, 4);

    // W_hh slice -> SMEM bf16 hi/lo (staging for fragment preload)
    for (int idx = tid; idx < 192 * 256; idx += 384) {
        int n = idx >> 8, k = idx & 255;
        int gate = n >> 6, jloc = n & 63;
        float v = Whh[((size_t)(gate * 256 + gj0 + jloc)) * 256 + k];
        __nv_bfloat16 hi = __float2bfloat16(v);
        Whi[n * BSTR + k] = hi;
        Wlo[n * BSTR + k] = __float2bfloat16(v - __bfloat162float(hi));
    }
    // H[0] init from hid0 (threads 0-255)
    if (tid < 256) {
        __nv_bfloat16* H0hi = (__nv_bfloat16*)(smem + OFF_H);
        __nv_bfloat16* H0lo = (__nv_bfloat16*)(smem + OFF_H + 4224);
        int b = tid >> 5, kg = (tid & 31) * 8;
#pragma unroll
        for (int i = 0; i < 8; i++) {
            float v = hid0[(size_t)(b0 + b) * 256 + kg + i];
            __nv_bfloat16 hi = __float2bfloat16(v);
            H0hi[b * BSTR + kg + i] = hi;
            H0lo[b * BSTR + kg + i] = __float2bfloat16(v - __bfloat162float(hi));
        }
    }
    for (int i = tid; i < 576; i += 384) f0stage[i] = 0.f;

    // per-thread gate items (threads 0-255): (bi, jA), (bi, jA+1)
    int bi = tid & 7, jA = (tid >> 3) * 2;
    float2 uR = {0, 0}, uZ = {0, 0}, uN = {0, 0}, bN = {0, 0}, pwv = {0, 0};
    float hA = 0, hB = 0;
    float postb = pb[0];
    if (tid < 256) {
        uR = *(const float2*)&g_u[gj0 + jA];
        uZ = *(const float2*)&g_u[256 + gj0 + jA];
        uN = *(const float2*)&g_u[512 + gj0 + jA];
        bN = *(const float2*)&bhh[512 + gj0 + jA];
        pwv = *(const float2*)&pw[gj0 + jA];
        hA = hid0[(size_t)(b0 + bi) * 256 + gj0 + jA];
        hB = hid0[(size_t)(b0 + bi) * 256 + gj0 + jA + 1];
    }
    __syncthreads();

    uint32_t aoff0 = (uint32_t)((wid * 16 + ((lane >> 3) & 1) * 8 + (lane & 7)) * BSTR +
                                (lane >> 4) * 8) * 2;
    // preload W fragments into registers (hi+lo, 16 k16-chunks each)
    uint32_t wh[64], wl[64];
    {
        uint32_t wHiA = smemB + OFF_WHI + aoff0;
        uint32_t wLoA = smemB + OFF_WLO + aoff0;
#pragma unroll
        for (int i = 0; i < 16; i++) {
            ldsm4(wHiA + i * 32, wh[i * 4 + 0], wh[i * 4 + 1], wh[i * 4 + 2], wh[i * 4 + 3]);
            ldsm4(wLoA + i * 32, wl[i * 4 + 0], wl[i * 4 + 1], wl[i * 4 + 2], wl[i * 4 + 3]);
        }
    }

    uint32_t hoff = (uint32_t)((lane & 7) * BSTR + (lane >> 3) * 8) * 2;
    uint32_t hHiA[2];
    hHiA[0] = smemB + OFF_H + hoff;
    hHiA[1] = smemB + OFF_H + HBUF + hoff;

    uint32_t peer[4];
#pragma unroll
    for (int r = 0; r < 4; r++)
        asm volatile("mapa.shared::cluster.u32 %0, %1, %2;" : "=r"(peer[r]) : "r"(smemB), "r"(r));

    uint32_t oHi = OFF_H + (uint32_t)(bi * BSTR + gj0 + jA) * 2;
    uint32_t oF0 = OFF_F0S + (uint32_t)(lane * 36 + rank * 8 + wid) * 4;

    // one-time cluster sync: mbarrier init + H/W staging visible before any remote arrive
    asm volatile("barrier.cluster.arrive.aligned;" ::: "memory");
    asm volatile("barrier.cluster.wait.aligned;" ::: "memory");

    for (int t = 0; t < Tn; t++) {
        int cur = t & 1, nxt = cur ^ 1;
        float aE[4] = {0.f, 0.f, 0.f, 0.f};
        float aO[4] = {0.f, 0.f, 0.f, 0.f};
        uint32_t hHi = hHiA[cur], hLo = hHi + 4224;
#pragma unroll
        for (int c = 0; c < 8; c++) {
            uint32_t hh0, hh1, hh2, hh3, hl0, hl1, hl2, hl3;
            ldsm4(hHi + c * 64, hh0, hh1, hh2, hh3);
            ldsm4(hLo + c * 64, hl0, hl1, hl2, hl3);
            int e = c * 8, o = c * 8 + 4;
            mma_bf16(aE, wh[e], wh[e + 1], wh[e + 2], wh[e + 3], hh0, hh1);
            mma_bf16(aE, wh[e], wh[e + 1], wh[e + 2], wh[e + 3], hl0, hl1);
            mma_bf16(aE, wl[e], wl[e + 1], wl[e + 2], wl[e + 3], hh0, hh1);
            mma_bf16(aO, wh[o], wh[o + 1], wh[o + 2], wh[o + 3], hh2, hh3);
            mma_bf16(aO, wh[o], wh[o + 1], wh[o + 2], wh[o + 3], hl2, hl3);
            mma_bf16(aO, wl[o], wl[o + 1], wl[o + 2], wl[o + 3], hh2, hh3);
        }

        // gi loads for THIS step (latency hidden under scatter + sync + f0 sum)
        float2 giR = {0, 0}, giZ = {0, 0}, giN = {0, 0};
        if (tid < 256) {
            size_t gb = ((size_t)t * 256 + b0 + bi) * 768;
            giR = *(const float2*)&g_gi[gb + gj0 + jA];
            giZ = *(const float2*)&g_gi[gb + 256 + gj0 + jA];
            giN = *(const float2*)&g_gi[gb + 512 + gj0 + jA];
        }

        // scatter pre-activations
        {
            int rr = lane >> 2, cb = (lane & 3) * 2;
            int m0r = wid * 16 + rr;
            s_pre[m0r * 9 + cb] = aE[0] + aO[0];
            s_pre[m0r * 9 + cb + 1] = aE[1] + aO[1];
            s_pre[(m0r + 8) * 9 + cb] = aE[2] + aO[2];
            s_pre[(m0r + 8) * 9 + cb + 1] = aE[3] + aO[3];
        }
        __syncthreads();

        if (tid < 256) {
            // f0 from 32 staged per-warp partials (buffer cur), vectorized
            float f0;
            {
                const float4* fs = (const float4*)(f0stage + cur * 288 + bi * 36);
                float4 v0 = fs[0], v1 = fs[1], v2 = fs[2], v3 = fs[3];
                float4 v4 = fs[4], v5 = fs[5], v6 = fs[6], v7 = fs[7];
                float s01 = (v0.x + v0.y) + (v0.z + v0.w);
                float s23 = (v1.x + v1.y) + (v1.z + v1.w);
                float s45 = (v2.x + v2.y) + (v2.z + v2.w);
                float s67 = (v3.x + v3.y) + (v3.z + v3.w);
                float s89 = (v4.x + v4.y) + (v4.z + v4.w);
                float sab = (v5.x + v5.y) + (v5.z + v5.w);
                float scd = (v6.x + v6.y) + (v6.z + v6.w);
                float sef = (v7.x + v7.y) + (v7.z + v7.w);
                float s = ((s01 + s23) + (s45 + s67)) + ((s89 + sab) + (scd + sef));
                f0 = (t == 0) ? 0.f : (s + postb);
            }
            if (rank == 0 && tid < 8 && t > 0) out[(size_t)(b0 + bi) * Tn + (t - 1)] = f0;

            // gate combine (items jA, jA+1) with fast activations
            float aR_A = s_pre[jA * 9 + bi], aZ_A = s_pre[(64 + jA) * 9 + bi], aN_A = s_pre[(128 + jA) * 9 + bi];
            float aR_B = s_pre[(jA + 1) * 9 + bi], aZ_B = s_pre[(65 + jA) * 9 + bi], aN_B = s_pre[(129 + jA) * 9 + bi];
            float rA = sigm_f(fmaf(uR.x, f0, giR.x) + aR_A);
            float zA = sigm_f(fmaf(uZ.x, f0, giZ.x) + aZ_A);
            float nA = tanh_f(fmaf(uN.x, f0, giN.x) + rA * (aN_A + bN.x));
            float hnA = (1.f - zA) * nA + zA * hA;
            float rB = sigm_f(fmaf(uR.y, f0, giR.y) + aR_B);
            float zB = sigm_f(fmaf(uZ.y, f0, giZ.y) + aZ_B);
            float nB = tanh_f(fmaf(uN.y, f0, giN.y) + rB * (aN_B + bN.y));
            float hnB = (1.f - zB) * nB + zB * hB;
            hA = hnA; hB = hnB;

            // hn exchange: packed bf16 pairs; local rank via STS, 3 peers via DSMEM
            {
                uint32_t hb = nxt * HBUF;
                __nv_bfloat16 hiA = __float2bfloat16(hnA);
                __nv_bfloat16 hiB = __float2bfloat16(hnB);
                uint32_t phi = (uint32_t)__bfloat16_as_ushort(hiA) |
                               ((uint32_t)__bfloat16_as_ushort(hiB) << 16);
                uint32_t plo = (uint32_t)__bfloat16_as_ushort(__float2bfloat16(hnA - __bfloat162float(hiA))) |
                               ((uint32_t)__bfloat16_as_ushort(__float2bfloat16(hnB - __bfloat162float(hiB))) << 16);
                sts32(smemB + oHi + hb, phi);
                sts32(smemB + oHi + hb + 4224, plo);
#pragma unroll
                for (int r = 0; r < 4; r++) {
                    if (r != rank) {
                        stc32(peer[r] + oHi + hb, phi);
                        stc32(peer[r] + oHi + hb + 4224, plo);
                    }
                }
            }

            // per-warp f0 partial -> f0stage[nxt] (local STS + 3 remote)
            float pf = fmaf(hnA, pwv.x, hnB * pwv.y);
            pf += __shfl_xor_sync(0xFFFFFFFFu, pf, 8);
            pf += __shfl_xor_sync(0xFFFFFFFFu, pf, 16);
            if (lane < 8) {
                uint32_t fb = nxt * 1152;
                sts32(smemB + oF0 + fb, __float_as_uint(pf));
#pragma unroll
                for (int r = 0; r < 4; r++)
                    if (r != rank) stc32(peer[r] + oF0 + fb, __float_as_uint(pf));
            }
        }

        // ---- mbarrier cluster sync (replaces barrier.cluster; no L1 flush) ----
        __syncthreads();   // all CTA threads done reading H[cur] + issuing stores
        if (tid == 0) {
            asm volatile("fence.acq_rel.cluster;" ::: "memory");
#pragma unroll
            for (int r = 0; r < 4; r++) mbar_arrive_cluster(peer[r] + OFF_MBAR);
        }
        mbar_wait(smemB + OFF_MBAR, (uint32_t)(t & 1));
    }

    // tail: out[Tn-1]
    if (rank == 0 && tid < 8) {
        const float* fs = f0stage + ((Tn & 1) * 288) + tid * 36;
        float s = 0.f;
#pragma unroll
        for (int q = 0; q < 32; q++) s += fs[q];
        out[(size_t)(b0 + tid) * Tn + (Tn - 1)] = s + postb;
    }
}

// ---------------- launcher ----------------
extern "C" void kernel_launch(void* const* d_in, const int* in_sizes, int n_in,
                              void* d_out, int out_size) {
    int off = (n_in >= 19) ? 1 : 0;
    const int* vw   = (const int*)d_in[off + 0];
    const int* cs   = (const int*)d_in[off + 1];
    const int* sa   = (const int*)d_in[off + 2];
    const int* ea   = (const int*)d_in[off + 3];
    const int* sap  = (const int*)d_in[off + 4];
    const int* eap  = (const int*)d_in[off + 5];
    const int* sid  = (const int*)d_in[off + 6];
    const float* hid0 = (const float*)d_in[off + 7];
    const float* pht  = (const float*)d_in[off + 8];
    const float* spt  = (const float*)d_in[off + 9];
    const float* encw = (const float*)d_in[off + 10];
    const float* encb = (const float*)d_in[off + 11];
    const float* Wih  = (const float*)d_in[off + 12];
    const float* Whh  = (const float*)d_in[off + 13];
    const float* bih  = (const float*)d_in[off + 14];
    const float* bhh  = (const float*)d_in[off + 15];
    const float* pw   = (const float*)d_in[off + 16];
    const float* pb   = (const float*)d_in[off + 17];
    float* out = (float*)d_out;

    k_setup<<<1722, 256>>>(pht, spt, sid, encw, Wih);
    k_enc<<<dim3(Tn / 4, Bn), 256>>>(vw, cs, sa, ea, sap, eap, encb);
    k_gemm<<<dim3(3, 2048), 256>>>(bih, bhh);

    cudaFuncSetAttribute(k_gru, cudaFuncAttributeMaxDynamicSharedMemorySize, SMEM3_BYTES);
    k_gru<<<128, 384, SMEM3_BYTES>>>(hid0, Whh, bhh, pw, pb, out);
}

// round 13
// speedup vs baseline: 1.1525x; 1.1525x over previous
#include <cuda_runtime.h>
#include <cuda_bf16.h>
#include <math.h>
#include <stdint.h>

#define Tn 1024
#define Bn 256

// ---------------- static device scratch ----------------
__device__ __align__(128) float g_pv[46 * 3 * 256];
__device__ __align__(128) float g_pa[16 * 3 * 256];
__device__ __align__(128) float g_pb[256 * 3 * 256];
__device__ __align__(128) __nv_bfloat16 g_Wb_hi[768 * 256];
__device__ __align__(128) __nv_bfloat16 g_Wb_lo[768 * 256];
__device__ __align__(128) float g_u[768];
__device__ __align__(128) __nv_bfloat16 g_h_hi[(size_t)262144 * 256];
__device__ __align__(128) __nv_bfloat16 g_h_lo[(size_t)262144 * 256];
__device__ __align__(128) float g_gi[(size_t)262144 * 768];

// fast, overflow-safe activations (MUFU-based; rel err ~1e-6)
__device__ __forceinline__ float sigm_f(float x) {
    return __fdividef(1.f, 1.f + __expf(-x));
}
__device__ __forceinline__ float tanh_f(float x) {
    float t = __expf(-2.f * fabsf(x));
    float r = __fdividef(1.f - t, 1.f + t);
    return copysignf(r, x);
}

// ---------------- K_setup ----------------
__global__ void k_setup(const float* __restrict__ ph, const float* __restrict__ spt,
                        const int* __restrict__ sid, const float* __restrict__ w,
                        const float* __restrict__ Wih) {
    int bid = blockIdx.x, c = threadIdx.x;
    if (bid < 138) {
        int p = bid / 3, k = bid % 3;
        float a = 0.f;
#pragma unroll 8
        for (int e = 0; e < 64; e++) a = fmaf(ph[p * 64 + e], w[c * 396 + e * 3 + k], a);
        g_pv[(p * 3 + k) * 256 + c] = a;
    } else if (bid < 186) {
        int m = (bid - 138) / 3, k = (bid - 138) % 3;
        float a = 0.f;
#pragma unroll
        for (int bit = 0; bit < 4; bit++)
            if ((m >> bit) & 1) a += w[c * 396 + (64 + bit) * 3 + k];
        g_pa[(m * 3 + k) * 256 + c] = a;
    } else if (bid < 954) {
        int b = (bid - 186) / 3, k = (bid - 186) % 3;
        int s0 = sid[b];
        float a = 0.f;
#pragma unroll 8
        for (int s = 0; s < 64; s++) a = fmaf(spt[s0 * 64 + s], w[c * 396 + (68 + s) * 3 + k], a);
        g_pb[(b * 3 + k) * 256 + c] = a;
    } else {
        int g = bid - 954;
        float v = Wih[g * 257 + c];
        __nv_bfloat16 hi = __float2bfloat16(v);
        __nv_bfloat16 lo = __float2bfloat16(v - __bfloat162float(hi));
        g_Wb_hi[g * 256 + c] = hi;
        g_Wb_lo[g * 256 + c] = lo;
        if (c == 0) g_u[g] = Wih[g * 257 + 256];
    }
}

// ---------------- K1: encoder (4 timesteps per block) ----------------
__global__ void k_enc(const int* __restrict__ vw, const int* __restrict__ cs,
                      const int* __restrict__ sa, const int* __restrict__ ea,
                      const int* __restrict__ sap, const int* __restrict__ eap,
                      const float* __restrict__ encb) {
    int t0 = blockIdx.x * 4, b = blockIdx.y, c = threadIdx.x;
    float bias = encb[c];
#pragma unroll
    for (int tt = 0; tt < 4; tt++) {
        int t = t0 + tt;
        float a = bias;
#pragma unroll
        for (int k = 0; k < 3; k++) {
            int tp = t + k - 1;
            if (tp < 0 || tp >= Tn) continue;
            int o = b * Tn + tp;
            int iv = vw[o] + 1;
            int ic = cs[o] + 1;
            int ia = sa[o] + 2 * ea[o] + 4 * sap[o] + 8 * eap[o];
            a += g_pv[(iv * 3 + k) * 256 + c] + g_pv[(ic * 3 + k) * 256 + c] +
                 g_pa[(ia * 3 + k) * 256 + c] + g_pb[(b * 3 + k) * 256 + c];
        }
        a = fmaxf(a, 0.f);
        __nv_bfloat16 hi = __float2bfloat16(a);
        __nv_bfloat16 lo = __float2bfloat16(a - __bfloat162float(hi));
        size_t idx = ((size_t)(t * 256 + b)) * 256 + c;
        g_h_hi[idx] = hi;
        g_h_lo[idx] = lo;
    }
}

// ---------------- mma helpers ----------------
__device__ __forceinline__ void ldsm4(uint32_t addr, uint32_t& r0, uint32_t& r1,
                                      uint32_t& r2, uint32_t& r3) {
    asm volatile("ldmatrix.sync.aligned.m8n8.x4.shared.b16 {%0,%1,%2,%3}, [%4];"
                 : "=r"(r0), "=r"(r1), "=r"(r2), "=r"(r3) : "r"(addr));
}
__device__ __forceinline__ void mma_bf16(float* c, uint32_t a0, uint32_t a1, uint32_t a2,
                                         uint32_t a3, uint32_t b0, uint32_t b1) {
    asm volatile("mma.sync.aligned.m16n8k16.row.col.f32.bf16.bf16.f32 "
                 "{%0,%1,%2,%3}, {%4,%5,%6,%7}, {%8,%9}, {%0,%1,%2,%3};"
                 : "+f"(c[0]), "+f"(c[1]), "+f"(c[2]), "+f"(c[3])
                 : "r"(a0), "r"(a1), "r"(a2), "r"(a3), "r"(b0), "r"(b1));
}

// ---------------- K2: tensor-core bf16-split GEMM ----------------
#define ASTR 40

__global__ __launch_bounds__(256, 2) void k_gemm(const float* __restrict__ bih,
                                                 const float* __restrict__ bhh) {
    __shared__ __nv_bfloat16 Ah[128 * ASTR], Al[128 * ASTR];
    __shared__ __nv_bfloat16 Bh[128 * ASTR], Bl[128 * ASTR];
    int tid = threadIdx.x, lane = tid & 31, wid = tid >> 5;
    int n0 = blockIdx.x * 128;
    size_t m0 = (size_t)blockIdx.y * 128;
    int wm = (wid & 1) * 64, wn = (wid >> 1) * 32;

    float acc[4][4][4];
#pragma unroll
    for (int i = 0; i < 4; i++)
#pragma unroll
        for (int j = 0; j < 4; j++)
#pragma unroll
            for (int r = 0; r < 4; r++) acc[i][j][r] = 0.f;

    uint32_t aHiB = (uint32_t)__cvta_generic_to_shared(Ah);
    uint32_t aLoB = (uint32_t)__cvta_generic_to_shared(Al);
    uint32_t bHiB = (uint32_t)__cvta_generic_to_shared(Bh);
    uint32_t bLoB = (uint32_t)__cvta_generic_to_shared(Bl);

    for (int kt = 0; kt < 8; kt++) {
        __syncthreads();
#pragma unroll
        for (int h = 0; h < 2; h++) {
            int q = tid + h * 256;
            int row = q >> 2, c = q & 3;
            size_t gsrc = (m0 + row) * 256 + kt * 32 + c * 8;
            *(uint4*)&Ah[row * ASTR + c * 8] = *(const uint4*)&g_h_hi[gsrc];
            *(uint4*)&Al[row * ASTR + c * 8] = *(const uint4*)&g_h_lo[gsrc];
            size_t bsrc = (size_t)(n0 + row) * 256 + kt * 32 + c * 8;
            *(uint4*)&Bh[row * ASTR + c * 8] = *(const uint4*)&g_Wb_hi[bsrc];
            *(uint4*)&Bl[row * ASTR + c * 8] = *(const uint4*)&g_Wb_lo[bsrc];
        }
        __syncthreads();

#pragma unroll
        for (int s = 0; s < 2; s++) {
            uint32_t bh[8], bl[8];
#pragma unroll
            for (int nh = 0; nh < 2; nh++) {
                int row = wn + nh * 16 + (lane >> 4) * 8 + (lane & 7);
                int kc8 = (lane >> 3) & 1;
                uint32_t off = (uint32_t)(row * ASTR + s * 16 + kc8 * 8) * 2;
                ldsm4(bHiB + off, bh[nh * 4 + 0], bh[nh * 4 + 1], bh[nh * 4 + 2], bh[nh * 4 + 3]);
                ldsm4(bLoB + off, bl[nh * 4 + 0], bl[nh * 4 + 1], bl[nh * 4 + 2], bl[nh * 4 + 3]);
            }
#pragma unroll
            for (int mi = 0; mi < 4; mi++) {
                int row = wm + mi * 16 + ((lane >> 3) & 1) * 8 + (lane & 7);
                int kc8 = lane >> 4;
                uint32_t off = (uint32_t)(row * ASTR + s * 16 + kc8 * 8) * 2;
                uint32_t ah0, ah1, ah2, ah3, al0, al1, al2, al3;
                ldsm4(aHiB + off, ah0, ah1, ah2, ah3);
                ldsm4(aLoB + off, al0, al1, al2, al3);
#pragma unroll
                for (int ni = 0; ni < 4; ni++) {
                    uint32_t b0h = bh[ni * 2], b1h = bh[ni * 2 + 1];
                    uint32_t b0l = bl[ni * 2], b1l = bl[ni * 2 + 1];
                    mma_bf16(acc[mi][ni], ah0, ah1, ah2, ah3, b0h, b1h);
                    mma_bf16(acc[mi][ni], ah0, ah1, ah2, ah3, b0l, b1l);
                    mma_bf16(acc[mi][ni], al0, al1, al2, al3, b0h, b1h);
                }
            }
        }
    }

    float bs0[4], bs1[4];
#pragma unroll
    for (int ni = 0; ni < 4; ni++) {
        int nc = n0 + wn + ni * 8 + (lane & 3) * 2;
        bs0[ni] = bih[nc] + (nc < 512 ? bhh[nc] : 0.f);
        bs1[ni] = bih[nc + 1] + (nc + 1 < 512 ? bhh[nc + 1] : 0.f);
    }
#pragma unroll
    for (int mi = 0; mi < 4; mi++) {
#pragma unroll
        for (int ni = 0; ni < 4; ni++) {
            int r = lane >> 2;
            int nc = n0 + wn + ni * 8 + (lane & 3) * 2;
            size_t row0 = m0 + wm + mi * 16 + r;
            float2 v0 = {acc[mi][ni][0] + bs0[ni], acc[mi][ni][1] + bs1[ni]};
            float2 v1 = {acc[mi][ni][2] + bs0[ni], acc[mi][ni][3] + bs1[ni]};
            *(float2*)&g_gi[row0 * 768 + nc] = v0;
            *(float2*)&g_gi[(row0 + 8) * 768 + nc] = v1;
        }
    }
}

// ---------------- K3: tensor-core GRU v9 (R10 + f0 hoist) ----------------
// 32 clusters x 4 CTAs, 384 threads (12 warps, one m16 tile each).
// Register-resident W; fast activations; f0 reduction hoisted to loop top
// (hidden in mma-phase issue slack instead of the serial gate tail).
#define BSTR 264
#define OFF_WHI 0
#define OFF_WLO 101376
#define OFF_H   202752          // H[buf]: buf*HBUF; hi at +0, lo at +4224
#define HBUF    8448
#define OFF_PRE 219648          // s_pre[192][9] f32 = 6912
#define OFF_F0S 226560          // f0stage[2][8][36] f32 = 2304
#define SMEM3_BYTES 228864

#define CARRIVE asm volatile("barrier.cluster.arrive.aligned;" ::: "memory")
#define CWAIT   asm volatile("barrier.cluster.wait.aligned;" ::: "memory")

__device__ __forceinline__ void stc32(uint32_t addr, uint32_t v) {
    asm volatile("st.shared::cluster.b32 [%0], %1;" :: "r"(addr), "r"(v));
}
__device__ __forceinline__ void sts32(uint32_t addr, uint32_t v) {
    asm volatile("st.shared.b32 [%0], %1;" :: "r"(addr), "r"(v));
}

__global__ void __cluster_dims__(4, 1, 1) __launch_bounds__(384, 1)
k_gru(const float* __restrict__ hid0, const float* __restrict__ Whh,
      const float* __restrict__ bhh, const float* __restrict__ pw,
      const float* __restrict__ pb, float* __restrict__ out) {
    extern __shared__ char smem[];
    __nv_bfloat16* Whi = (__nv_bfloat16*)(smem + OFF_WHI);
    __nv_bfloat16* Wlo = (__nv_bfloat16*)(smem + OFF_WLO);
    float* s_pre = (float*)(smem + OFF_PRE);
    float* f0stage = (float*)(smem + OFF_F0S);

    int tid = threadIdx.x, lane = tid & 31, wid = tid >> 5;
    int cid = blockIdx.x >> 2, rank = blockIdx.x & 3;
    int b0 = cid * 8, gj0 = rank * 64;

    // W_hh slice -> SMEM bf16 hi/lo (staging for fragment preload)
    for (int idx = tid; idx < 192 * 256; idx += 384) {
        int n = idx >> 8, k = idx & 255;
        int gate = n >> 6, jloc = n & 63;
        float v = Whh[((size_t)(gate * 256 + gj0 + jloc)) * 256 + k];
        __nv_bfloat16 hi = __float2bfloat16(v);
        Whi[n * BSTR + k] = hi;
        Wlo[n * BSTR + k] = __float2bfloat16(v - __bfloat162float(hi));
    }
    // H[0] init from hid0 (threads 0-255)
    if (tid < 256) {
        __nv_bfloat16* H0hi = (__nv_bfloat16*)(smem + OFF_H);
        __nv_bfloat16* H0lo = (__nv_bfloat16*)(smem + OFF_H + 4224);
        int b = tid >> 5, kg = (tid & 31) * 8;
#pragma unroll
        for (int i = 0; i < 8; i++) {
            float v = hid0[(size_t)(b0 + b) * 256 + kg + i];
            __nv_bfloat16 hi = __float2bfloat16(v);
            H0hi[b * BSTR + kg + i] = hi;
            H0lo[b * BSTR + kg + i] = __float2bfloat16(v - __bfloat162float(hi));
        }
    }
    for (int i = tid; i < 576; i += 384) f0stage[i] = 0.f;

    // per-thread gate items (threads 0-255): (bi, jA), (bi, jA+1)
    int bi = tid & 7, jA = (tid >> 3) * 2;
    float2 uR = {0, 0}, uZ = {0, 0}, uN = {0, 0}, bN = {0, 0}, pwv = {0, 0};
    float hA = 0, hB = 0;
    float postb = pb[0];
    if (tid < 256) {
        uR = *(const float2*)&g_u[gj0 + jA];
        uZ = *(const float2*)&g_u[256 + gj0 + jA];
        uN = *(const float2*)&g_u[512 + gj0 + jA];
        bN = *(const float2*)&bhh[512 + gj0 + jA];
        pwv = *(const float2*)&pw[gj0 + jA];
        hA = hid0[(size_t)(b0 + bi) * 256 + gj0 + jA];
        hB = hid0[(size_t)(b0 + bi) * 256 + gj0 + jA + 1];
    }
    __syncthreads();

    uint32_t smemB = (uint32_t)__cvta_generic_to_shared(smem);
    uint32_t aoff0 = (uint32_t)((wid * 16 + ((lane >> 3) & 1) * 8 + (lane & 7)) * BSTR +
                                (lane >> 4) * 8) * 2;
    // preload W fragments into registers (hi+lo, 16 k16-chunks each)
    uint32_t wh[64], wl[64];
    {
        uint32_t wHiA = smemB + OFF_WHI + aoff0;
        uint32_t wLoA = smemB + OFF_WLO + aoff0;
#pragma unroll
        for (int i = 0; i < 16; i++) {
            ldsm4(wHiA + i * 32, wh[i * 4 + 0], wh[i * 4 + 1], wh[i * 4 + 2], wh[i * 4 + 3]);
            ldsm4(wLoA + i * 32, wl[i * 4 + 0], wl[i * 4 + 1], wl[i * 4 + 2], wl[i * 4 + 3]);
        }
    }

    uint32_t hoff = (uint32_t)((lane & 7) * BSTR + (lane >> 3) * 8) * 2;
    uint32_t hHiA[2];
    hHiA[0] = smemB + OFF_H + hoff;
    hHiA[1] = smemB + OFF_H + HBUF + hoff;

    uint32_t peer[4];
#pragma unroll
    for (int r = 0; r < 4; r++)
        asm volatile("mapa.shared::cluster.u32 %0, %1, %2;" : "=r"(peer[r]) : "r"(smemB), "r"(r));

    uint32_t oHi = OFF_H + (uint32_t)(bi * BSTR + gj0 + jA) * 2;
    uint32_t oF0 = OFF_F0S + (uint32_t)(lane * 36 + rank * 8 + wid) * 4;

    for (int t = 0; t < Tn; t++) {
        int cur = t & 1, nxt = cur ^ 1;

        // ---- f0 reduction HOISTED: f0stage[cur] is valid at loop top; the
        // LDS+add chain overlaps the mma phase instead of the serial tail ----
        float f0 = 0.f;
        if (tid < 256) {
            const float4* fs = (const float4*)(f0stage + cur * 288 + bi * 36);
            float4 v0 = fs[0], v1 = fs[1], v2 = fs[2], v3 = fs[3];
            float4 v4 = fs[4], v5 = fs[5], v6 = fs[6], v7 = fs[7];
            float s01 = (v0.x + v0.y) + (v0.z + v0.w);
            float s23 = (v1.x + v1.y) + (v1.z + v1.w);
            float s45 = (v2.x + v2.y) + (v2.z + v2.w);
            float s67 = (v3.x + v3.y) + (v3.z + v3.w);
            float s89 = (v4.x + v4.y) + (v4.z + v4.w);
            float sab = (v5.x + v5.y) + (v5.z + v5.w);
            float scd = (v6.x + v6.y) + (v6.z + v6.w);
            float sef = (v7.x + v7.y) + (v7.z + v7.w);
            float s = ((s01 + s23) + (s45 + s67)) + ((s89 + sab) + (scd + sef));
            f0 = (t == 0) ? 0.f : (s + postb);
            if (rank == 0 && tid < 8 && t > 0) out[(size_t)(b0 + bi) * Tn + (t - 1)] = f0;
        }

        float aE[4] = {0.f, 0.f, 0.f, 0.f};
        float aO[4] = {0.f, 0.f, 0.f, 0.f};
        uint32_t hHi = hHiA[cur], hLo = hHi + 4224;
#pragma unroll
        for (int c = 0; c < 8; c++) {
            uint32_t hh0, hh1, hh2, hh3, hl0, hl1, hl2, hl3;
            ldsm4(hHi + c * 64, hh0, hh1, hh2, hh3);
            ldsm4(hLo + c * 64, hl0, hl1, hl2, hl3);
            int e = c * 8, o = c * 8 + 4;
            mma_bf16(aE, wh[e], wh[e + 1], wh[e + 2], wh[e + 3], hh0, hh1);
            mma_bf16(aE, wh[e], wh[e + 1], wh[e + 2], wh[e + 3], hl0, hl1);
            mma_bf16(aE, wl[e], wl[e + 1], wl[e + 2], wl[e + 3], hh0, hh1);
            mma_bf16(aO, wh[o], wh[o + 1], wh[o + 2], wh[o + 3], hh2, hh3);
            mma_bf16(aO, wh[o], wh[o + 1], wh[o + 2], wh[o + 3], hl2, hl3);
            mma_bf16(aO, wl[o], wl[o + 1], wl[o + 2], wl[o + 3], hh2, hh3);
        }

        // gi loads for THIS step (latency hidden under scatter + sync)
        float2 giR = {0, 0}, giZ = {0, 0}, giN = {0, 0};
        if (tid < 256) {
            size_t gb = ((size_t)t * 256 + b0 + bi) * 768;
            giR = *(const float2*)&g_gi[gb + gj0 + jA];
            giZ = *(const float2*)&g_gi[gb + 256 + gj0 + jA];
            giN = *(const float2*)&g_gi[gb + 512 + gj0 + jA];
        }

        // scatter pre-activations
        {
            int rr = lane >> 2, cb = (lane & 3) * 2;
            int m0r = wid * 16 + rr;
            s_pre[m0r * 9 + cb] = aE[0] + aO[0];
            s_pre[m0r * 9 + cb + 1] = aE[1] + aO[1];
            s_pre[(m0r + 8) * 9 + cb] = aE[2] + aO[2];
            s_pre[(m0r + 8) * 9 + cb + 1] = aE[3] + aO[3];
        }
        __syncthreads();

        if (tid < 256) {
            // gate combine (items jA, jA+1) with fast activations
            float aR_A = s_pre[jA * 9 + bi], aZ_A = s_pre[(64 + jA) * 9 + bi], aN_A = s_pre[(128 + jA) * 9 + bi];
            float aR_B = s_pre[(jA + 1) * 9 + bi], aZ_B = s_pre[(65 + jA) * 9 + bi], aN_B = s_pre[(129 + jA) * 9 + bi];
            float rA = sigm_f(fmaf(uR.x, f0, giR.x) + aR_A);
            float zA = sigm_f(fmaf(uZ.x, f0, giZ.x) + aZ_A);
            float nA = tanh_f(fmaf(uN.x, f0, giN.x) + rA * (aN_A + bN.x));
            float hnA = (1.f - zA) * nA + zA * hA;
            float rB = sigm_f(fmaf(uR.y, f0, giR.y) + aR_B);
            float zB = sigm_f(fmaf(uZ.y, f0, giZ.y) + aZ_B);
            float nB = tanh_f(fmaf(uN.y, f0, giN.y) + rB * (aN_B + bN.y));
            float hnB = (1.f - zB) * nB + zB * hB;
            hA = hnA; hB = hnB;

            // hn exchange: packed bf16 pairs; local rank via STS, 3 peers via DSMEM
            {
                uint32_t hb = nxt * HBUF;
                __nv_bfloat16 hiA = __float2bfloat16(hnA);
                __nv_bfloat16 hiB = __float2bfloat16(hnB);
                uint32_t phi = (uint32_t)__bfloat16_as_ushort(hiA) |
                               ((uint32_t)__bfloat16_as_ushort(hiB) << 16);
                uint32_t plo = (uint32_t)__bfloat16_as_ushort(__float2bfloat16(hnA - __bfloat162float(hiA))) |
                               ((uint32_t)__bfloat16_as_ushort(__float2bfloat16(hnB - __bfloat162float(hiB))) << 16);
                sts32(smemB + oHi + hb, phi);
                sts32(smemB + oHi + hb + 4224, plo);
#pragma unroll
                for (int r = 0; r < 4; r++) {
                    if (r != rank) {
                        stc32(peer[r] + oHi + hb, phi);
                        stc32(peer[r] + oHi + hb + 4224, plo);
                    }
                }
            }

            // per-warp f0 partial -> f0stage[nxt] (local STS + 3 remote)
            float pf = fmaf(hnA, pwv.x, hnB * pwv.y);
            pf += __shfl_xor_sync(0xFFFFFFFFu, pf, 8);
            pf += __shfl_xor_sync(0xFFFFFFFFu, pf, 16);
            if (lane < 8) {
                uint32_t fb = nxt * 1152;
                sts32(smemB + oF0 + fb, __float_as_uint(pf));
#pragma unroll
                for (int r = 0; r < 4; r++)
                    if (r != rank) stc32(peer[r] + oF0 + fb, __float_as_uint(pf));
            }
        }

        CARRIVE;   // release DSMEM writes
        CWAIT;     // all CTAs' writes visible
    }

    // tail: out[Tn-1]
    if (rank == 0 && tid < 8) {
        const float* fs = f0stage + ((Tn & 1) * 288) + tid * 36;
        float s = 0.f;
#pragma unroll
        for (int q = 0; q < 32; q++) s += fs[q];
        out[(size_t)(b0 + tid) * Tn + (Tn - 1)] = s + postb;
    }
}

// ---------------- launcher ----------------
extern "C" void kernel_launch(void* const* d_in, const int* in_sizes, int n_in,
                              void* d_out, int out_size) {
    int off = (n_in >= 19) ? 1 : 0;
    const int* vw   = (const int*)d_in[off + 0];
    const int* cs   = (const int*)d_in[off + 1];
    const int* sa   = (const int*)d_in[off + 2];
    const int* ea   = (const int*)d_in[off + 3];
    const int* sap  = (const int*)d_in[off + 4];
    const int* eap  = (const int*)d_in[off + 5];
    const int* sid  = (const int*)d_in[off + 6];
    const float* hid0 = (const float*)d_in[off + 7];
    const float* pht  = (const float*)d_in[off + 8];
    const float* spt  = (const float*)d_in[off + 9];
    const float* encw = (const float*)d_in[off + 10];
    const float* encb = (const float*)d_in[off + 11];
    const float* Wih  = (const float*)d_in[off + 12];
    const float* Whh  = (const float*)d_in[off + 13];
    const float* bih  = (const float*)d_in[off + 14];
    const float* bhh  = (const float*)d_in[off + 15];
    const float* pw   = (const float*)d_in[off + 16];
    const float* pb   = (const float*)d_in[off + 17];
    float* out = (float*)d_out;

    k_setup<<<1722, 256>>>(pht, spt, sid, encw, Wih);
    k_enc<<<dim3(Tn / 4, Bn), 256>>>(vw, cs, sa, ea, sap, eap, encb);
    k_gemm<<<dim3(6, 2048), 256>>>(bih, bhh);

    cudaFuncSetAttribute(k_gru, cudaFuncAttributeMaxDynamicSharedMemorySize, SMEM3_BYTES);
    k_gru<<<128, 384, SMEM3_BYTES>>>(hid0, Whh, bhh, pw, pb, out);
}

// round 14
// speedup vs baseline: 1.2289x; 1.0663x over previous
#include <cuda_runtime.h>
#include <cuda_bf16.h>
#include <math.h>
#include <stdint.h>

#define Tn 1024
#define Bn 256

// ---------------- static device scratch ----------------
__device__ __align__(128) float g_pv[46 * 3 * 256];
__device__ __align__(128) float g_pa[16 * 3 * 256];
__device__ __align__(128) float g_pb[256 * 3 * 256];
__device__ __align__(128) __nv_bfloat16 g_Wb_hi[768 * 256];
__device__ __align__(128) __nv_bfloat16 g_Wb_lo[768 * 256];
__device__ __align__(128) float g_u[768];
__device__ __align__(128) __nv_bfloat16 g_h_hi[(size_t)262144 * 256];
__device__ __align__(128) __nv_bfloat16 g_h_lo[(size_t)262144 * 256];
__device__ __align__(128) float g_gi[(size_t)262144 * 768];

// fast, overflow-safe activations (MUFU-based; rel err ~1e-6)
__device__ __forceinline__ float sigm_f(float x) {
    return __fdividef(1.f, 1.f + __expf(-x));
}
__device__ __forceinline__ float tanh_f(float x) {
    float t = __expf(-2.f * fabsf(x));
    float r = __fdividef(1.f - t, 1.f + t);
    return copysignf(r, x);
}

// ---------------- K_setup ----------------
__global__ void k_setup(const float* __restrict__ ph, const float* __restrict__ spt,
                        const int* __restrict__ sid, const float* __restrict__ w,
                        const float* __restrict__ Wih) {
    int bid = blockIdx.x, c = threadIdx.x;
    if (bid < 138) {
        int p = bid / 3, k = bid % 3;
        float a = 0.f;
#pragma unroll 8
        for (int e = 0; e < 64; e++) a = fmaf(ph[p * 64 + e], w[c * 396 + e * 3 + k], a);
        g_pv[(p * 3 + k) * 256 + c] = a;
    } else if (bid < 186) {
        int m = (bid - 138) / 3, k = (bid - 138) % 3;
        float a = 0.f;
#pragma unroll
        for (int bit = 0; bit < 4; bit++)
            if ((m >> bit) & 1) a += w[c * 396 + (64 + bit) * 3 + k];
        g_pa[(m * 3 + k) * 256 + c] = a;
    } else if (bid < 954) {
        int b = (bid - 186) / 3, k = (bid - 186) % 3;
        int s0 = sid[b];
        float a = 0.f;
#pragma unroll 8
        for (int s = 0; s < 64; s++) a = fmaf(spt[s0 * 64 + s], w[c * 396 + (68 + s) * 3 + k], a);
        g_pb[(b * 3 + k) * 256 + c] = a;
    } else {
        int g = bid - 954;
        float v = Wih[g * 257 + c];
        __nv_bfloat16 hi = __float2bfloat16(v);
        __nv_bfloat16 lo = __float2bfloat16(v - __bfloat162float(hi));
        g_Wb_hi[g * 256 + c] = hi;
        g_Wb_lo[g * 256 + c] = lo;
        if (c == 0) g_u[g] = Wih[g * 257 + 256];
    }
}

// ---------------- K1: encoder (4 timesteps per block) ----------------
__global__ void k_enc(const int* __restrict__ vw, const int* __restrict__ cs,
                      const int* __restrict__ sa, const int* __restrict__ ea,
                      const int* __restrict__ sap, const int* __restrict__ eap,
                      const float* __restrict__ encb) {
    int t0 = blockIdx.x * 4, b = blockIdx.y, c = threadIdx.x;
    float bias = encb[c];
#pragma unroll
    for (int tt = 0; tt < 4; tt++) {
        int t = t0 + tt;
        float a = bias;
#pragma unroll
        for (int k = 0; k < 3; k++) {
            int tp = t + k - 1;
            if (tp < 0 || tp >= Tn) continue;
            int o = b * Tn + tp;
            int iv = vw[o] + 1;
            int ic = cs[o] + 1;
            int ia = sa[o] + 2 * ea[o] + 4 * sap[o] + 8 * eap[o];
            a += g_pv[(iv * 3 + k) * 256 + c] + g_pv[(ic * 3 + k) * 256 + c] +
                 g_pa[(ia * 3 + k) * 256 + c] + g_pb[(b * 3 + k) * 256 + c];
        }
        a = fmaxf(a, 0.f);
        __nv_bfloat16 hi = __float2bfloat16(a);
        __nv_bfloat16 lo = __float2bfloat16(a - __bfloat162float(hi));
        size_t idx = ((size_t)(t * 256 + b)) * 256 + c;
        g_h_hi[idx] = hi;
        g_h_lo[idx] = lo;
    }
}

// ---------------- mma helpers ----------------
__device__ __forceinline__ void ldsm4(uint32_t addr, uint32_t& r0, uint32_t& r1,
                                      uint32_t& r2, uint32_t& r3) {
    asm volatile("ldmatrix.sync.aligned.m8n8.x4.shared.b16 {%0,%1,%2,%3}, [%4];"
                 : "=r"(r0), "=r"(r1), "=r"(r2), "=r"(r3) : "r"(addr));
}
__device__ __forceinline__ void mma_bf16(float* c, uint32_t a0, uint32_t a1, uint32_t a2,
                                         uint32_t a3, uint32_t b0, uint32_t b1) {
    asm volatile("mma.sync.aligned.m16n8k16.row.col.f32.bf16.bf16.f32 "
                 "{%0,%1,%2,%3}, {%4,%5,%6,%7}, {%8,%9}, {%0,%1,%2,%3};"
                 : "+f"(c[0]), "+f"(c[1]), "+f"(c[2]), "+f"(c[3])
                 : "r"(a0), "r"(a1), "r"(a2), "r"(a3), "r"(b0), "r"(b1));
}
__device__ __forceinline__ void cpa16(uint32_t saddr, const void* g) {
    asm volatile("cp.async.cg.shared.global [%0], [%1], 16;" :: "r"(saddr), "l"(g));
}
#define CP_COMMIT asm volatile("cp.async.commit_group;" ::: "memory")

// ---------------- K2: tensor-core bf16-split GEMM (2-stage cp.async) ----------------
#define ASTR 40
#define ARR_B 10240                 // one array (128 rows x 80B)
#define STG_B (4 * ARR_B)           // stage: Ah|Al|Bh|Bl
#define GSMEM (2 * STG_B)           // 81920 bytes

__global__ __launch_bounds__(256, 2) void k_gemm(const float* __restrict__ bih,
                                                 const float* __restrict__ bhh) {
    extern __shared__ char gsm[];
    int tid = threadIdx.x, lane = tid & 31, wid = tid >> 5;
    int n0 = blockIdx.x * 128;
    size_t m0 = (size_t)blockIdx.y * 128;
    int wm = (wid & 1) * 64, wn = (wid >> 1) * 32;

    float acc[4][4][4];
#pragma unroll
    for (int i = 0; i < 4; i++)
#pragma unroll
        for (int j = 0; j < 4; j++)
#pragma unroll
            for (int r = 0; r < 4; r++) acc[i][j][r] = 0.f;

    uint32_t smB = (uint32_t)__cvta_generic_to_shared(gsm);
    int row = tid >> 2, cq = tid & 3;
    int rowOff = row * 80 + cq * 16;

    // issue loads for k-chunk kt into stage stg
    auto issue = [&](int kt, int stg) {
        uint32_t sb = smB + stg * STG_B;
#pragma unroll
        for (int h = 0; h < 2; h++) {
            int r2 = row + h * 64;
            uint32_t ro = (uint32_t)(r2 * 80 + cq * 16);
            size_t gA = (m0 + r2) * 256 + kt * 32 + cq * 8;
            size_t gB = (size_t)(n0 + r2) * 256 + kt * 32 + cq * 8;
            cpa16(sb + ro, &g_h_hi[gA]);
            cpa16(sb + ARR_B + ro, &g_h_lo[gA]);
            cpa16(sb + 2 * ARR_B + ro, &g_Wb_hi[gB]);
            cpa16(sb + 3 * ARR_B + ro, &g_Wb_lo[gB]);
        }
    };

    issue(0, 0);
    CP_COMMIT;

    for (int kt = 0; kt < 8; kt++) {
        if (kt < 7) {
            issue(kt + 1, (kt + 1) & 1);
            CP_COMMIT;
            asm volatile("cp.async.wait_group 1;" ::: "memory");
        } else {
            asm volatile("cp.async.wait_group 0;" ::: "memory");
        }
        __syncthreads();

        uint32_t sb = smB + (kt & 1) * STG_B;
        uint32_t aHiB = sb, aLoB = sb + ARR_B, bHiB = sb + 2 * ARR_B, bLoB = sb + 3 * ARR_B;

#pragma unroll
        for (int s = 0; s < 2; s++) {
            uint32_t bh[8], bl[8];
#pragma unroll
            for (int nh = 0; nh < 2; nh++) {
                int rr = wn + nh * 16 + (lane >> 4) * 8 + (lane & 7);
                int kc8 = (lane >> 3) & 1;
                uint32_t off = (uint32_t)(rr * ASTR + s * 16 + kc8 * 8) * 2;
                ldsm4(bHiB + off, bh[nh * 4 + 0], bh[nh * 4 + 1], bh[nh * 4 + 2], bh[nh * 4 + 3]);
                ldsm4(bLoB + off, bl[nh * 4 + 0], bl[nh * 4 + 1], bl[nh * 4 + 2], bl[nh * 4 + 3]);
            }
#pragma unroll
            for (int mi = 0; mi < 4; mi++) {
                int rr = wm + mi * 16 + ((lane >> 3) & 1) * 8 + (lane & 7);
                int kc8 = lane >> 4;
                uint32_t off = (uint32_t)(rr * ASTR + s * 16 + kc8 * 8) * 2;
                uint32_t ah0, ah1, ah2, ah3, al0, al1, al2, al3;
                ldsm4(aHiB + off, ah0, ah1, ah2, ah3);
                ldsm4(aLoB + off, al0, al1, al2, al3);
#pragma unroll
                for (int ni = 0; ni < 4; ni++) {
                    uint32_t b0h = bh[ni * 2], b1h = bh[ni * 2 + 1];
                    uint32_t b0l = bl[ni * 2], b1l = bl[ni * 2 + 1];
                    mma_bf16(acc[mi][ni], ah0, ah1, ah2, ah3, b0h, b1h);
                    mma_bf16(acc[mi][ni], ah0, ah1, ah2, ah3, b0l, b1l);
                    mma_bf16(acc[mi][ni], al0, al1, al2, al3, b0h, b1h);
                }
            }
        }
        __syncthreads();   // all compute on this stage done before its re-fill
    }

    float bs0[4], bs1[4];
#pragma unroll
    for (int ni = 0; ni < 4; ni++) {
        int nc = n0 + wn + ni * 8 + (lane & 3) * 2;
        bs0[ni] = bih[nc] + (nc < 512 ? bhh[nc] : 0.f);
        bs1[ni] = bih[nc + 1] + (nc + 1 < 512 ? bhh[nc + 1] : 0.f);
    }
#pragma unroll
    for (int mi = 0; mi < 4; mi++) {
#pragma unroll
        for (int ni = 0; ni < 4; ni++) {
            int r = lane >> 2;
            int nc = n0 + wn + ni * 8 + (lane & 3) * 2;
            size_t row0 = m0 + wm + mi * 16 + r;
            float2 v0 = {acc[mi][ni][0] + bs0[ni], acc[mi][ni][1] + bs1[ni]};
            float2 v1 = {acc[mi][ni][2] + bs0[ni], acc[mi][ni][3] + bs1[ni]};
            *(float2*)&g_gi[row0 * 768 + nc] = v0;
            *(float2*)&g_gi[(row0 + 8) * 768 + nc] = v1;
        }
    }
}

// ---------------- K3: tensor-core GRU (R10-best, unchanged) ----------------
#define BSTR 264
#define OFF_WHI 0
#define OFF_WLO 101376
#define OFF_H   202752
#define HBUF    8448
#define OFF_PRE 219648
#define OFF_F0S 226560
#define SMEM3_BYTES 228864

#define CARRIVE asm volatile("barrier.cluster.arrive.aligned;" ::: "memory")
#define CWAIT   asm volatile("barrier.cluster.wait.aligned;" ::: "memory")

__device__ __forceinline__ void stc32(uint32_t addr, uint32_t v) {
    asm volatile("st.shared::cluster.b32 [%0], %1;" :: "r"(addr), "r"(v));
}
__device__ __forceinline__ void sts32(uint32_t addr, uint32_t v) {
    asm volatile("st.shared.b32 [%0], %1;" :: "r"(addr), "r"(v));
}

__global__ void __cluster_dims__(4, 1, 1) __launch_bounds__(384, 1)
k_gru(const float* __restrict__ hid0, const float* __restrict__ Whh,
      const float* __restrict__ bhh, const float* __restrict__ pw,
      const float* __restrict__ pb, float* __restrict__ out) {
    extern __shared__ char smem[];
    __nv_bfloat16* Whi = (__nv_bfloat16*)(smem + OFF_WHI);
    __nv_bfloat16* Wlo = (__nv_bfloat16*)(smem + OFF_WLO);
    float* s_pre = (float*)(smem + OFF_PRE);
    float* f0stage = (float*)(smem + OFF_F0S);

    int tid = threadIdx.x, lane = tid & 31, wid = tid >> 5;
    int cid = blockIdx.x >> 2, rank = blockIdx.x & 3;
    int b0 = cid * 8, gj0 = rank * 64;

    for (int idx = tid; idx < 192 * 256; idx += 384) {
        int n = idx >> 8, k = idx & 255;
        int gate = n >> 6, jloc = n & 63;
        float v = Whh[((size_t)(gate * 256 + gj0 + jloc)) * 256 + k];
        __nv_bfloat16 hi = __float2bfloat16(v);
        Whi[n * BSTR + k] = hi;
        Wlo[n * BSTR + k] = __float2bfloat16(v - __bfloat162float(hi));
    }
    if (tid < 256) {
        __nv_bfloat16* H0hi = (__nv_bfloat16*)(smem + OFF_H);
        __nv_bfloat16* H0lo = (__nv_bfloat16*)(smem + OFF_H + 4224);
        int b = tid >> 5, kg = (tid & 31) * 8;
#pragma unroll
        for (int i = 0; i < 8; i++) {
            float v = hid0[(size_t)(b0 + b) * 256 + kg + i];
            __nv_bfloat16 hi = __float2bfloat16(v);
            H0hi[b * BSTR + kg + i] = hi;
            H0lo[b * BSTR + kg + i] = __float2bfloat16(v - __bfloat162float(hi));
        }
    }
    for (int i = tid; i < 576; i += 384) f0stage[i] = 0.f;

    int bi = tid & 7, jA = (tid >> 3) * 2;
    float2 uR = {0, 0}, uZ = {0, 0}, uN = {0, 0}, bN = {0, 0}, pwv = {0, 0};
    float hA = 0, hB = 0;
    float postb = pb[0];
    if (tid < 256) {
        uR = *(const float2*)&g_u[gj0 + jA];
        uZ = *(const float2*)&g_u[256 + gj0 + jA];
        uN = *(const float2*)&g_u[512 + gj0 + jA];
        bN = *(const float2*)&bhh[512 + gj0 + jA];
        pwv = *(const float2*)&pw[gj0 + jA];
        hA = hid0[(size_t)(b0 + bi) * 256 + gj0 + jA];
        hB = hid0[(size_t)(b0 + bi) * 256 + gj0 + jA + 1];
    }
    __syncthreads();

    uint32_t smemB = (uint32_t)__cvta_generic_to_shared(smem);
    uint32_t aoff0 = (uint32_t)((wid * 16 + ((lane >> 3) & 1) * 8 + (lane & 7)) * BSTR +
                                (lane >> 4) * 8) * 2;
    uint32_t wh[64], wl[64];
    {
        uint32_t wHiA = smemB + OFF_WHI + aoff0;
        uint32_t wLoA = smemB + OFF_WLO + aoff0;
#pragma unroll
        for (int i = 0; i < 16; i++) {
            ldsm4(wHiA + i * 32, wh[i * 4 + 0], wh[i * 4 + 1], wh[i * 4 + 2], wh[i * 4 + 3]);
            ldsm4(wLoA + i * 32, wl[i * 4 + 0], wl[i * 4 + 1], wl[i * 4 + 2], wl[i * 4 + 3]);
        }
    }

    uint32_t hoff = (uint32_t)((lane & 7) * BSTR + (lane >> 3) * 8) * 2;
    uint32_t hHiA[2];
    hHiA[0] = smemB + OFF_H + hoff;
    hHiA[1] = smemB + OFF_H + HBUF + hoff;

    uint32_t peer[4];
#pragma unroll
    for (int r = 0; r < 4; r++)
        asm volatile("mapa.shared::cluster.u32 %0, %1, %2;" : "=r"(peer[r]) : "r"(smemB), "r"(r));

    uint32_t oHi = OFF_H + (uint32_t)(bi * BSTR + gj0 + jA) * 2;
    uint32_t oF0 = OFF_F0S + (uint32_t)(lane * 36 + rank * 8 + wid) * 4;

    for (int t = 0; t < Tn; t++) {
        int cur = t & 1, nxt = cur ^ 1;
        float aE[4] = {0.f, 0.f, 0.f, 0.f};
        float aO[4] = {0.f, 0.f, 0.f, 0.f};
        uint32_t hHi = hHiA[cur], hLo = hHi + 4224;
#pragma unroll
        for (int c = 0; c < 8; c++) {
            uint32_t hh0, hh1, hh2, hh3, hl0, hl1, hl2, hl3;
            ldsm4(hHi + c * 64, hh0, hh1, hh2, hh3);
            ldsm4(hLo + c * 64, hl0, hl1, hl2, hl3);
            int e = c * 8, o = c * 8 + 4;
            mma_bf16(aE, wh[e], wh[e + 1], wh[e + 2], wh[e + 3], hh0, hh1);
            mma_bf16(aE, wh[e], wh[e + 1], wh[e + 2], wh[e + 3], hl0, hl1);
            mma_bf16(aE, wl[e], wl[e + 1], wl[e + 2], wl[e + 3], hh0, hh1);
            mma_bf16(aO, wh[o], wh[o + 1], wh[o + 2], wh[o + 3], hh2, hh3);
            mma_bf16(aO, wh[o], wh[o + 1], wh[o + 2], wh[o + 3], hl2, hl3);
            mma_bf16(aO, wl[o], wl[o + 1], wl[o + 2], wl[o + 3], hh2, hh3);
        }

        float2 giR = {0, 0}, giZ = {0, 0}, giN = {0, 0};
        if (tid < 256) {
            size_t gb = ((size_t)t * 256 + b0 + bi) * 768;
            giR = *(const float2*)&g_gi[gb + gj0 + jA];
            giZ = *(const float2*)&g_gi[gb + 256 + gj0 + jA];
            giN = *(const float2*)&g_gi[gb + 512 + gj0 + jA];
        }

        {
            int rr = lane >> 2, cb = (lane & 3) * 2;
            int m0r = wid * 16 + rr;
            s_pre[m0r * 9 + cb] = aE[0] + aO[0];
            s_pre[m0r * 9 + cb + 1] = aE[1] + aO[1];
            s_pre[(m0r + 8) * 9 + cb] = aE[2] + aO[2];
            s_pre[(m0r + 8) * 9 + cb + 1] = aE[3] + aO[3];
        }
        __syncthreads();

        if (tid < 256) {
            float f0;
            {
                const float4* fs = (const float4*)(f0stage + cur * 288 + bi * 36);
                float4 v0 = fs[0], v1 = fs[1], v2 = fs[2], v3 = fs[3];
                float4 v4 = fs[4], v5 = fs[5], v6 = fs[6], v7 = fs[7];
                float s01 = (v0.x + v0.y) + (v0.z + v0.w);
                float s23 = (v1.x + v1.y) + (v1.z + v1.w);
                float s45 = (v2.x + v2.y) + (v2.z + v2.w);
                float s67 = (v3.x + v3.y) + (v3.z + v3.w);
                float s89 = (v4.x + v4.y) + (v4.z + v4.w);
                float sab = (v5.x + v5.y) + (v5.z + v5.w);
                float scd = (v6.x + v6.y) + (v6.z + v6.w);
                float sef = (v7.x + v7.y) + (v7.z + v7.w);
                float s = ((s01 + s23) + (s45 + s67)) + ((s89 + sab) + (scd + sef));
                f0 = (t == 0) ? 0.f : (s + postb);
            }
            if (rank == 0 && tid < 8 && t > 0) out[(size_t)(b0 + bi) * Tn + (t - 1)] = f0;

            float aR_A = s_pre[jA * 9 + bi], aZ_A = s_pre[(64 + jA) * 9 + bi], aN_A = s_pre[(128 + jA) * 9 + bi];
            float aR_B = s_pre[(jA + 1) * 9 + bi], aZ_B = s_pre[(65 + jA) * 9 + bi], aN_B = s_pre[(129 + jA) * 9 + bi];
            float rA = sigm_f(fmaf(uR.x, f0, giR.x) + aR_A);
            float zA = sigm_f(fmaf(uZ.x, f0, giZ.x) + aZ_A);
            float nA = tanh_f(fmaf(uN.x, f0, giN.x) + rA * (aN_A + bN.x));
            float hnA = (1.f - zA) * nA + zA * hA;
            float rB = sigm_f(fmaf(uR.y, f0, giR.y) + aR_B);
            float zB = sigm_f(fmaf(uZ.y, f0, giZ.y) + aZ_B);
            float nB = tanh_f(fmaf(uN.y, f0, giN.y) + rB * (aN_B + bN.y));
            float hnB = (1.f - zB) * nB + zB * hB;
            hA = hnA; hB = hnB;

            {
                uint32_t hb = nxt * HBUF;
                __nv_bfloat16 hiA = __float2bfloat16(hnA);
                __nv_bfloat16 hiB = __float2bfloat16(hnB);
                uint32_t phi = (uint32_t)__bfloat16_as_ushort(hiA) |
                               ((uint32_t)__bfloat16_as_ushort(hiB) << 16);
                uint32_t plo = (uint32_t)__bfloat16_as_ushort(__float2bfloat16(hnA - __bfloat162float(hiA))) |
                               ((uint32_t)__bfloat16_as_ushort(__float2bfloat16(hnB - __bfloat162float(hiB))) << 16);
                sts32(smemB + oHi + hb, phi);
                sts32(smemB + oHi + hb + 4224, plo);
#pragma unroll
                for (int r = 0; r < 4; r++) {
                    if (r != rank) {
                        stc32(peer[r] + oHi + hb, phi);
                        stc32(peer[r] + oHi + hb + 4224, plo);
                    }
                }
            }

            float pf = fmaf(hnA, pwv.x, hnB * pwv.y);
            pf += __shfl_xor_sync(0xFFFFFFFFu, pf, 8);
            pf += __shfl_xor_sync(0xFFFFFFFFu, pf, 16);
            if (lane < 8) {
                uint32_t fb = nxt * 1152;
                sts32(smemB + oF0 + fb, __float_as_uint(pf));
#pragma unroll
                for (int r = 0; r < 4; r++)
                    if (r != rank) stc32(peer[r] + oF0 + fb, __float_as_uint(pf));
            }
        }

        CARRIVE;
        CWAIT;
    }

    if (rank == 0 && tid < 8) {
        const float* fs = f0stage + ((Tn & 1) * 288) + tid * 36;
        float s = 0.f;
#pragma unroll
        for (int q = 0; q < 32; q++) s += fs[q];
        out[(size_t)(b0 + tid) * Tn + (Tn - 1)] = s + postb;
    }
}

// ---------------- launcher ----------------
extern "C" void kernel_launch(void* const* d_in, const int* in_sizes, int n_in,
                              void* d_out, int out_size) {
    int off = (n_in >= 19) ? 1 : 0;
    const int* vw   = (const int*)d_in[off + 0];
    const int* cs   = (const int*)d_in[off + 1];
    const int* sa   = (const int*)d_in[off + 2];
    const int* ea   = (const int*)d_in[off + 3];
    const int* sap  = (const int*)d_in[off + 4];
    const int* eap  = (const int*)d_in[off + 5];
    const int* sid  = (const int*)d_in[off + 6];
    const float* hid0 = (const float*)d_in[off + 7];
    const float* pht  = (const float*)d_in[off + 8];
    const float* spt  = (const float*)d_in[off + 9];
    const float* encw = (const float*)d_in[off + 10];
    const float* encb = (const float*)d_in[off + 11];
    const float* Wih  = (const float*)d_in[off + 12];
    const float* Whh  = (const float*)d_in[off + 13];
    const float* bih  = (const float*)d_in[off + 14];
    const float* bhh  = (const float*)d_in[off + 15];
    const float* pw   = (const float*)d_in[off + 16];
    const float* pb   = (const float*)d_in[off + 17];
    float* out = (float*)d_out;

    k_setup<<<1722, 256>>>(pht, spt, sid, encw, Wih);
    k_enc<<<dim3(Tn / 4, Bn), 256>>>(vw, cs, sa, ea, sap, eap, encb);

    cudaFuncSetAttribute(k_gemm, cudaFuncAttributeMaxDynamicSharedMemorySize, GSMEM);
    k_gemm<<<dim3(6, 2048), 256, GSMEM>>>(bih, bhh);

    cudaFuncSetAttribute(k_gru, cudaFuncAttributeMaxDynamicSharedMemorySize, SMEM3_BYTES);
    k_gru<<<128, 384, SMEM3_BYTES>>>(hid0, Whh, bhh, pw, pb, out);
}

// round 15
// speedup vs baseline: 1.2864x; 1.0468x over previous
#include <cuda_runtime.h>
#include <cuda_bf16.h>
#include <math.h>
#include <stdint.h>

#define Tn 1024
#define Bn 256

// ---------------- static device scratch ----------------
__device__ __align__(128) float g_pv[46 * 3 * 256];
__device__ __align__(128) float g_pa[16 * 3 * 256];
__device__ __align__(128) float g_pb[256 * 3 * 256];
__device__ __align__(128) __nv_bfloat16 g_Wb_hi[768 * 256];
__device__ __align__(128) __nv_bfloat16 g_Wb_lo[768 * 256];
__device__ __align__(128) float g_u[768];
__device__ __align__(128) __nv_bfloat16 g_h_hi[(size_t)262144 * 256];
__device__ __align__(128) __nv_bfloat16 g_h_lo[(size_t)262144 * 256];
__device__ __align__(128) float g_gi[(size_t)262144 * 768];

// fast, overflow-safe activations (MUFU-based; rel err ~1e-6)
__device__ __forceinline__ float sigm_f(float x) {
    return __fdividef(1.f, 1.f + __expf(-x));
}
__device__ __forceinline__ float tanh_f(float x) {
    float t = __expf(-2.f * fabsf(x));
    float r = __fdividef(1.f - t, 1.f + t);
    return copysignf(r, x);
}

// ---------------- K_setup ----------------
__global__ void k_setup(const float* __restrict__ ph, const float* __restrict__ spt,
                        const int* __restrict__ sid, const float* __restrict__ w,
                        const float* __restrict__ Wih) {
    int bid = blockIdx.x, c = threadIdx.x;
    if (bid < 138) {
        int p = bid / 3, k = bid % 3;
        float a = 0.f;
#pragma unroll 8
        for (int e = 0; e < 64; e++) a = fmaf(ph[p * 64 + e], w[c * 396 + e * 3 + k], a);
        g_pv[(p * 3 + k) * 256 + c] = a;
    } else if (bid < 186) {
        int m = (bid - 138) / 3, k = (bid - 138) % 3;
        float a = 0.f;
#pragma unroll
        for (int bit = 0; bit < 4; bit++)
            if ((m >> bit) & 1) a += w[c * 396 + (64 + bit) * 3 + k];
        g_pa[(m * 3 + k) * 256 + c] = a;
    } else if (bid < 954) {
        int b = (bid - 186) / 3, k = (bid - 186) % 3;
        int s0 = sid[b];
        float a = 0.f;
#pragma unroll 8
        for (int s = 0; s < 64; s++) a = fmaf(spt[s0 * 64 + s], w[c * 396 + (68 + s) * 3 + k], a);
        g_pb[(b * 3 + k) * 256 + c] = a;
    } else {
        int g = bid - 954;
        float v = Wih[g * 257 + c];
        __nv_bfloat16 hi = __float2bfloat16(v);
        __nv_bfloat16 lo = __float2bfloat16(v - __bfloat162float(hi));
        g_Wb_hi[g * 256 + c] = hi;
        g_Wb_lo[g * 256 + c] = lo;
        if (c == 0) g_u[g] = Wih[g * 257 + 256];
    }
}

// ---------------- K1: encoder v2 (8 timesteps/block, shared indices) ----------------
__global__ void k_enc(const int* __restrict__ vw, const int* __restrict__ cs,
                      const int* __restrict__ sa, const int* __restrict__ ea,
                      const int* __restrict__ sap, const int* __restrict__ eap,
                      const float* __restrict__ encb) {
    __shared__ int s_iv[10], s_ic[10], s_ia[10];
    int t0 = blockIdx.x * 8, b = blockIdx.y, c = threadIdx.x;

    if (c < 10) {
        int tp = t0 - 1 + c;
        if (tp >= 0 && tp < Tn) {
            int o = b * Tn + tp;
            s_iv[c] = vw[o] + 1;
            s_ic[c] = cs[o] + 1;
            s_ia[c] = sa[o] + 2 * ea[o] + 4 * sap[o] + 8 * eap[o];
        } else {
            s_iv[c] = -1;
            s_ic[c] = 0;
            s_ia[c] = 0;
        }
    }
    float bias = encb[c];
    float pbk[3];
#pragma unroll
    for (int k = 0; k < 3; k++) pbk[k] = g_pb[(b * 3 + k) * 256 + c];
    __syncthreads();

#pragma unroll
    for (int tt = 0; tt < 8; tt++) {
        int t = t0 + tt;
        float a = bias;
#pragma unroll
        for (int k = 0; k < 3; k++) {
            int i = tt + k;                    // tp = t0 - 1 + i = t + k - 1
            int iv = s_iv[i];
            if (iv >= 0) {
                a += g_pv[(iv * 3 + k) * 256 + c] + g_pv[(s_ic[i] * 3 + k) * 256 + c] +
                     g_pa[(s_ia[i] * 3 + k) * 256 + c] + pbk[k];
            }
        }
        a = fmaxf(a, 0.f);
        __nv_bfloat16 hi = __float2bfloat16(a);
        __nv_bfloat16 lo = __float2bfloat16(a - __bfloat162float(hi));
        size_t idx = ((size_t)(t * 256 + b)) * 256 + c;
        g_h_hi[idx] = hi;
        g_h_lo[idx] = lo;
    }
}

// ---------------- mma helpers ----------------
__device__ __forceinline__ void ldsm4(uint32_t addr, uint32_t& r0, uint32_t& r1,
                                      uint32_t& r2, uint32_t& r3) {
    asm volatile("ldmatrix.sync.aligned.m8n8.x4.shared.b16 {%0,%1,%2,%3}, [%4];"
                 : "=r"(r0), "=r"(r1), "=r"(r2), "=r"(r3) : "r"(addr));
}
__device__ __forceinline__ void mma_bf16(float* c, uint32_t a0, uint32_t a1, uint32_t a2,
                                         uint32_t a3, uint32_t b0, uint32_t b1) {
    asm volatile("mma.sync.aligned.m16n8k16.row.col.f32.bf16.bf16.f32 "
                 "{%0,%1,%2,%3}, {%4,%5,%6,%7}, {%8,%9}, {%0,%1,%2,%3};"
                 : "+f"(c[0]), "+f"(c[1]), "+f"(c[2]), "+f"(c[3])
                 : "r"(a0), "r"(a1), "r"(a2), "r"(a3), "r"(b0), "r"(b1));
}
__device__ __forceinline__ void cpa16(uint32_t saddr, const void* g) {
    asm volatile("cp.async.cg.shared.global [%0], [%1], 16;" :: "r"(saddr), "l"(g));
}
#define CP_COMMIT asm volatile("cp.async.commit_group;" ::: "memory")

// ---------------- K2: tensor-core bf16-split GEMM (2-stage cp.async) ----------------
#define ASTR 40
#define ARR_B 10240
#define STG_B (4 * ARR_B)
#define GSMEM (2 * STG_B)

__global__ __launch_bounds__(256, 2) void k_gemm(const float* __restrict__ bih,
                                                 const float* __restrict__ bhh) {
    extern __shared__ char gsm[];
    int tid = threadIdx.x, lane = tid & 31, wid = tid >> 5;
    int n0 = blockIdx.x * 128;
    size_t m0 = (size_t)blockIdx.y * 128;
    int wm = (wid & 1) * 64, wn = (wid >> 1) * 32;

    float acc[4][4][4];
#pragma unroll
    for (int i = 0; i < 4; i++)
#pragma unroll
        for (int j = 0; j < 4; j++)
#pragma unroll
            for (int r = 0; r < 4; r++) acc[i][j][r] = 0.f;

    uint32_t smB = (uint32_t)__cvta_generic_to_shared(gsm);
    int row = tid >> 2, cq = tid & 3;

    auto issue = [&](int kt, int stg) {
        uint32_t sb = smB + stg * STG_B;
#pragma unroll
        for (int h = 0; h < 2; h++) {
            int r2 = row + h * 64;
            uint32_t ro = (uint32_t)(r2 * 80 + cq * 16);
            size_t gA = (m0 + r2) * 256 + kt * 32 + cq * 8;
            size_t gB = (size_t)(n0 + r2) * 256 + kt * 32 + cq * 8;
            cpa16(sb + ro, &g_h_hi[gA]);
            cpa16(sb + ARR_B + ro, &g_h_lo[gA]);
            cpa16(sb + 2 * ARR_B + ro, &g_Wb_hi[gB]);
            cpa16(sb + 3 * ARR_B + ro, &g_Wb_lo[gB]);
        }
    };

    issue(0, 0);
    CP_COMMIT;

    for (int kt = 0; kt < 8; kt++) {
        if (kt < 7) {
            issue(kt + 1, (kt + 1) & 1);
            CP_COMMIT;
            asm volatile("cp.async.wait_group 1;" ::: "memory");
        } else {
            asm volatile("cp.async.wait_group 0;" ::: "memory");
        }
        __syncthreads();

        uint32_t sb = smB + (kt & 1) * STG_B;
        uint32_t aHiB = sb, aLoB = sb + ARR_B, bHiB = sb + 2 * ARR_B, bLoB = sb + 3 * ARR_B;

#pragma unroll
        for (int s = 0; s < 2; s++) {
            uint32_t bh[8], bl[8];
#pragma unroll
            for (int nh = 0; nh < 2; nh++) {
                int rr = wn + nh * 16 + (lane >> 4) * 8 + (lane & 7);
                int kc8 = (lane >> 3) & 1;
                uint32_t off = (uint32_t)(rr * ASTR + s * 16 + kc8 * 8) * 2;
                ldsm4(bHiB + off, bh[nh * 4 + 0], bh[nh * 4 + 1], bh[nh * 4 + 2], bh[nh * 4 + 3]);
                ldsm4(bLoB + off, bl[nh * 4 + 0], bl[nh * 4 + 1], bl[nh * 4 + 2], bl[nh * 4 + 3]);
            }
#pragma unroll
            for (int mi = 0; mi < 4; mi++) {
                int rr = wm + mi * 16 + ((lane >> 3) & 1) * 8 + (lane & 7);
                int kc8 = lane >> 4;
                uint32_t off = (uint32_t)(rr * ASTR + s * 16 + kc8 * 8) * 2;
                uint32_t ah0, ah1, ah2, ah3, al0, al1, al2, al3;
                ldsm4(aHiB + off, ah0, ah1, ah2, ah3);
                ldsm4(aLoB + off, al0, al1, al2, al3);
#pragma unroll
                for (int ni = 0; ni < 4; ni++) {
                    uint32_t b0h = bh[ni * 2], b1h = bh[ni * 2 + 1];
                    uint32_t b0l = bl[ni * 2], b1l = bl[ni * 2 + 1];
                    mma_bf16(acc[mi][ni], ah0, ah1, ah2, ah3, b0h, b1h);
                    mma_bf16(acc[mi][ni], ah0, ah1, ah2, ah3, b0l, b1l);
                    mma_bf16(acc[mi][ni], al0, al1, al2, al3, b0h, b1h);
                }
            }
        }
        __syncthreads();
    }

    float bs0[4], bs1[4];
#pragma unroll
    for (int ni = 0; ni < 4; ni++) {
        int nc = n0 + wn + ni * 8 + (lane & 3) * 2;
        bs0[ni] = bih[nc] + (nc < 512 ? bhh[nc] : 0.f);
        bs1[ni] = bih[nc + 1] + (nc + 1 < 512 ? bhh[nc + 1] : 0.f);
    }
#pragma unroll
    for (int mi = 0; mi < 4; mi++) {
#pragma unroll
        for (int ni = 0; ni < 4; ni++) {
            int r = lane >> 2;
            int nc = n0 + wn + ni * 8 + (lane & 3) * 2;
            size_t row0 = m0 + wm + mi * 16 + r;
            float2 v0 = {acc[mi][ni][0] + bs0[ni], acc[mi][ni][1] + bs1[ni]};
            float2 v1 = {acc[mi][ni][2] + bs0[ni], acc[mi][ni][3] + bs1[ni]};
            *(float2*)&g_gi[row0 * 768 + nc] = v0;
            *(float2*)&g_gi[(row0 + 8) * 768 + nc] = v1;
        }
    }
}

// ---------------- K3: tensor-core GRU (R10-best, unchanged) ----------------
#define BSTR 264
#define OFF_WHI 0
#define OFF_WLO 101376
#define OFF_H   202752
#define HBUF    8448
#define OFF_PRE 219648
#define OFF_F0S 226560
#define SMEM3_BYTES 228864

#define CARRIVE asm volatile("barrier.cluster.arrive.aligned;" ::: "memory")
#define CWAIT   asm volatile("barrier.cluster.wait.aligned;" ::: "memory")

__device__ __forceinline__ void stc32(uint32_t addr, uint32_t v) {
    asm volatile("st.shared::cluster.b32 [%0], %1;" :: "r"(addr), "r"(v));
}
__device__ __forceinline__ void sts32(uint32_t addr, uint32_t v) {
    asm volatile("st.shared.b32 [%0], %1;" :: "r"(addr), "r"(v));
}

__global__ void __cluster_dims__(4, 1, 1) __launch_bounds__(384, 1)
k_gru(const float* __restrict__ hid0, const float* __restrict__ Whh,
      const float* __restrict__ bhh, const float* __restrict__ pw,
      const float* __restrict__ pb, float* __restrict__ out) {
    extern __shared__ char smem[];
    __nv_bfloat16* Whi = (__nv_bfloat16*)(smem + OFF_WHI);
    __nv_bfloat16* Wlo = (__nv_bfloat16*)(smem + OFF_WLO);
    float* s_pre = (float*)(smem + OFF_PRE);
    float* f0stage = (float*)(smem + OFF_F0S);

    int tid = threadIdx.x, lane = tid & 31, wid = tid >> 5;
    int cid = blockIdx.x >> 2, rank = blockIdx.x & 3;
    int b0 = cid * 8, gj0 = rank * 64;

    for (int idx = tid; idx < 192 * 256; idx += 384) {
        int n = idx >> 8, k = idx & 255;
        int gate = n >> 6, jloc = n & 63;
        float v = Whh[((size_t)(gate * 256 + gj0 + jloc)) * 256 + k];
        __nv_bfloat16 hi = __float2bfloat16(v);
        Whi[n * BSTR + k] = hi;
        Wlo[n * BSTR + k] = __float2bfloat16(v - __bfloat162float(hi));
    }
    if (tid < 256) {
        __nv_bfloat16* H0hi = (__nv_bfloat16*)(smem + OFF_H);
        __nv_bfloat16* H0lo = (__nv_bfloat16*)(smem + OFF_H + 4224);
        int b = tid >> 5, kg = (tid & 31) * 8;
#pragma unroll
        for (int i = 0; i < 8; i++) {
            float v = hid0[(size_t)(b0 + b) * 256 + kg + i];
            __nv_bfloat16 hi = __float2bfloat16(v);
            H0hi[b * BSTR + kg + i] = hi;
            H0lo[b * BSTR + kg + i] = __float2bfloat16(v - __bfloat162float(hi));
        }
    }
    for (int i = tid; i < 576; i += 384) f0stage[i] = 0.f;

    int bi = tid & 7, jA = (tid >> 3) * 2;
    float2 uR = {0, 0}, uZ = {0, 0}, uN = {0, 0}, bN = {0, 0}, pwv = {0, 0};
    float hA = 0, hB = 0;
    float postb = pb[0];
    if (tid < 256) {
        uR = *(const float2*)&g_u[gj0 + jA];
        uZ = *(const float2*)&g_u[256 + gj0 + jA];
        uN = *(const float2*)&g_u[512 + gj0 + jA];
        bN = *(const float2*)&bhh[512 + gj0 + jA];
        pwv = *(const float2*)&pw[gj0 + jA];
        hA = hid0[(size_t)(b0 + bi) * 256 + gj0 + jA];
        hB = hid0[(size_t)(b0 + bi) * 256 + gj0 + jA + 1];
    }
    __syncthreads();

    uint32_t smemB = (uint32_t)__cvta_generic_to_shared(smem);
    uint32_t aoff0 = (uint32_t)((wid * 16 + ((lane >> 3) & 1) * 8 + (lane & 7)) * BSTR +
                                (lane >> 4) * 8) * 2;
    uint32_t wh[64], wl[64];
    {
        uint32_t wHiA = smemB + OFF_WHI + aoff0;
        uint32_t wLoA = smemB + OFF_WLO + aoff0;
#pragma unroll
        for (int i = 0; i < 16; i++) {
            ldsm4(wHiA + i * 32, wh[i * 4 + 0], wh[i * 4 + 1], wh[i * 4 + 2], wh[i * 4 + 3]);
            ldsm4(wLoA + i * 32, wl[i * 4 + 0], wl[i * 4 + 1], wl[i * 4 + 2], wl[i * 4 + 3]);
        }
    }

    uint32_t hoff = (uint32_t)((lane & 7) * BSTR + (lane >> 3) * 8) * 2;
    uint32_t hHiA[2];
    hHiA[0] = smemB + OFF_H + hoff;
    hHiA[1] = smemB + OFF_H + HBUF + hoff;

    uint32_t peer[4];
#pragma unroll
    for (int r = 0; r < 4; r++)
        asm volatile("mapa.shared::cluster.u32 %0, %1, %2;" : "=r"(peer[r]) : "r"(smemB), "r"(r));

    uint32_t oHi = OFF_H + (uint32_t)(bi * BSTR + gj0 + jA) * 2;
    uint32_t oF0 = OFF_F0S + (uint32_t)(lane * 36 + rank * 8 + wid) * 4;

    for (int t = 0; t < Tn; t++) {
        int cur = t & 1, nxt = cur ^ 1;
        float aE[4] = {0.f, 0.f, 0.f, 0.f};
        float aO[4] = {0.f, 0.f, 0.f, 0.f};
        uint32_t hHi = hHiA[cur], hLo = hHi + 4224;
#pragma unroll
        for (int c = 0; c < 8; c++) {
            uint32_t hh0, hh1, hh2, hh3, hl0, hl1, hl2, hl3;
            ldsm4(hHi + c * 64, hh0, hh1, hh2, hh3);
            ldsm4(hLo + c * 64, hl0, hl1, hl2, hl3);
            int e = c * 8, o = c * 8 + 4;
            mma_bf16(aE, wh[e], wh[e + 1], wh[e + 2], wh[e + 3], hh0, hh1);
            mma_bf16(aE, wh[e], wh[e + 1], wh[e + 2], wh[e + 3], hl0, hl1);
            mma_bf16(aE, wl[e], wl[e + 1], wl[e + 2], wl[e + 3], hh0, hh1);
            mma_bf16(aO, wh[o], wh[o + 1], wh[o + 2], wh[o + 3], hh2, hh3);
            mma_bf16(aO, wh[o], wh[o + 1], wh[o + 2], wh[o + 3], hl2, hl3);
            mma_bf16(aO, wl[o], wl[o + 1], wl[o + 2], wl[o + 3], hh2, hh3);
        }

        float2 giR = {0, 0}, giZ = {0, 0}, giN = {0, 0};
        if (tid < 256) {
            size_t gb = ((size_t)t * 256 + b0 + bi) * 768;
            giR = *(const float2*)&g_gi[gb + gj0 + jA];
            giZ = *(const float2*)&g_gi[gb + 256 + gj0 + jA];
            giN = *(const float2*)&g_gi[gb + 512 + gj0 + jA];
        }

        {
            int rr = lane >> 2, cb = (lane & 3) * 2;
            int m0r = wid * 16 + rr;
            s_pre[m0r * 9 + cb] = aE[0] + aO[0];
            s_pre[m0r * 9 + cb + 1] = aE[1] + aO[1];
            s_pre[(m0r + 8) * 9 + cb] = aE[2] + aO[2];
            s_pre[(m0r + 8) * 9 + cb + 1] = aE[3] + aO[3];
        }
        __syncthreads();

        if (tid < 256) {
            float f0;
            {
                const float4* fs = (const float4*)(f0stage + cur * 288 + bi * 36);
                float4 v0 = fs[0], v1 = fs[1], v2 = fs[2], v3 = fs[3];
                float4 v4 = fs[4], v5 = fs[5], v6 = fs[6], v7 = fs[7];
                float s01 = (v0.x + v0.y) + (v0.z + v0.w);
                float s23 = (v1.x + v1.y) + (v1.z + v1.w);
                float s45 = (v2.x + v2.y) + (v2.z + v2.w);
                float s67 = (v3.x + v3.y) + (v3.z + v3.w);
                float s89 = (v4.x + v4.y) + (v4.z + v4.w);
                float sab = (v5.x + v5.y) + (v5.z + v5.w);
                float scd = (v6.x + v6.y) + (v6.z + v6.w);
                float sef = (v7.x + v7.y) + (v7.z + v7.w);
                float s = ((s01 + s23) + (s45 + s67)) + ((s89 + sab) + (scd + sef));
                f0 = (t == 0) ? 0.f : (s + postb);
            }
            if (rank == 0 && tid < 8 && t > 0) out[(size_t)(b0 + bi) * Tn + (t - 1)] = f0;

            float aR_A = s_pre[jA * 9 + bi], aZ_A = s_pre[(64 + jA) * 9 + bi], aN_A = s_pre[(128 + jA) * 9 + bi];
            float aR_B = s_pre[(jA + 1) * 9 + bi], aZ_B = s_pre[(65 + jA) * 9 + bi], aN_B = s_pre[(129 + jA) * 9 + bi];
            float rA = sigm_f(fmaf(uR.x, f0, giR.x) + aR_A);
            float zA = sigm_f(fmaf(uZ.x, f0, giZ.x) + aZ_A);
            float nA = tanh_f(fmaf(uN.x, f0, giN.x) + rA * (aN_A + bN.x));
            float hnA = (1.f - zA) * nA + zA * hA;
            float rB = sigm_f(fmaf(uR.y, f0, giR.y) + aR_B);
            float zB = sigm_f(fmaf(uZ.y, f0, giZ.y) + aZ_B);
            float nB = tanh_f(fmaf(uN.y, f0, giN.y) + rB * (aN_B + bN.y));
            float hnB = (1.f - zB) * nB + zB * hB;
            hA = hnA; hB = hnB;

            {
                uint32_t hb = nxt * HBUF;
                __nv_bfloat16 hiA = __float2bfloat16(hnA);
                __nv_bfloat16 hiB = __float2bfloat16(hnB);
                uint32_t phi = (uint32_t)__bfloat16_as_ushort(hiA) |
                               ((uint32_t)__bfloat16_as_ushort(hiB) << 16);
                uint32_t plo = (uint32_t)__bfloat16_as_ushort(__float2bfloat16(hnA - __bfloat162float(hiA))) |
                               ((uint32_t)__bfloat16_as_ushort(__float2bfloat16(hnB - __bfloat162float(hiB))) << 16);
                sts32(smemB + oHi + hb, phi);
                sts32(smemB + oHi + hb + 4224, plo);
#pragma unroll
                for (int r = 0; r < 4; r++) {
                    if (r != rank) {
                        stc32(peer[r] + oHi + hb, phi);
                        stc32(peer[r] + oHi + hb + 4224, plo);
                    }
                }
            }

            float pf = fmaf(hnA, pwv.x, hnB * pwv.y);
            pf += __shfl_xor_sync(0xFFFFFFFFu, pf, 8);
            pf += __shfl_xor_sync(0xFFFFFFFFu, pf, 16);
            if (lane < 8) {
                uint32_t fb = nxt * 1152;
                sts32(smemB + oF0 + fb, __float_as_uint(pf));
#pragma unroll
                for (int r = 0; r < 4; r++)
                    if (r != rank) stc32(peer[r] + oF0 + fb, __float_as_uint(pf));
            }
        }

        CARRIVE;
        CWAIT;
    }

    if (rank == 0 && tid < 8) {
        const float* fs = f0stage + ((Tn & 1) * 288) + tid * 36;
        float s = 0.f;
#pragma unroll
        for (int q = 0; q < 32; q++) s += fs[q];
        out[(size_t)(b0 + tid) * Tn + (Tn - 1)] = s + postb;
    }
}

// ---------------- launcher ----------------
extern "C" void kernel_launch(void* const* d_in, const int* in_sizes, int n_in,
                              void* d_out, int out_size) {
    int off = (n_in >= 19) ? 1 : 0;
    const int* vw   = (const int*)d_in[off + 0];
    const int* cs   = (const int*)d_in[off + 1];
    const int* sa   = (const int*)d_in[off + 2];
    const int* ea   = (const int*)d_in[off + 3];
    const int* sap  = (const int*)d_in[off + 4];
    const int* eap  = (const int*)d_in[off + 5];
    const int* sid  = (const int*)d_in[off + 6];
    const float* hid0 = (const float*)d_in[off + 7];
    const float* pht  = (const float*)d_in[off + 8];
    const float* spt  = (const float*)d_in[off + 9];
    const float* encw = (const float*)d_in[off + 10];
    const float* encb = (const float*)d_in[off + 11];
    const float* Wih  = (const float*)d_in[off + 12];
    const float* Whh  = (const float*)d_in[off + 13];
    const float* bih  = (const float*)d_in[off + 14];
    const float* bhh  = (const float*)d_in[off + 15];
    const float* pw   = (const float*)d_in[off + 16];
    const float* pb   = (const float*)d_in[off + 17];
    float* out = (float*)d_out;

    k_setup<<<1722, 256>>>(pht, spt, sid, encw, Wih);
    k_enc<<<dim3(Tn / 8, Bn), 256>>>(vw, cs, sa, ea, sap, eap, encb);

    cudaFuncSetAttribute(k_gemm, cudaFuncAttributeMaxDynamicSharedMemorySize, GSMEM);
    k_gemm<<<dim3(6, 2048), 256, GSMEM>>>(bih, bhh);

    cudaFuncSetAttribute(k_gru, cudaFuncAttributeMaxDynamicSharedMemorySize, SMEM3_BYTES);
    k_gru<<<128, 384, SMEM3_BYTES>>>(hid0, Whh, bhh, pw, pb, out);
}